// round 3
// baseline (speedup 1.0000x reference)
#include <cuda_runtime.h>
#include <cuda_bf16.h>
#include <math.h>

// ---------------------------------------------------------------------------
// EmformerEncoder  B=2, T=1248, D=1024, H=16, DK=64, F=4096, L=2.
// Analytic block-sparse mask (CHUNK=128, LEFT=128, RIGHT=32).
// Round 2: pre-split bf16 hi/lo operands + cp.async double-buffered HMMA GEMM,
//          fused QKV GEMM, warp-per-query key-parallel attention.
// ---------------------------------------------------------------------------

#define TTOT   1248
#define NRIGHT 224
#define BATCH  2
#define MROWS  (BATCH * TTOT)   // 2496
#define DMODEL 1024
#define NHEAD  16
#define DK     64
#define FDIM   4096
#define QKVW   3072

// ---- scratch (device globals) ---------------------------------------------
__device__ float g_h[MROWS * DMODEL];
__device__ float g_attn[MROWS * DMODEL];
__device__ float g_y1[MROWS * FDIM];
__device__ float g_y2[MROWS * DMODEL];
__device__ float g_x[MROWS * DMODEL];
__device__ float g_qkv[MROWS * QKVW];
__device__ __nv_bfloat16 g_ah[MROWS * FDIM];   // activation split (max width F)
__device__ __nv_bfloat16 g_al[MROWS * FDIM];
__device__ unsigned g_wqkvh[2][(DMODEL/2) * QKVW];
__device__ unsigned g_wqkvl[2][(DMODEL/2) * QKVW];
__device__ unsigned g_w1h[2][(DMODEL/2) * FDIM];
__device__ unsigned g_w1l[2][(DMODEL/2) * FDIM];
__device__ unsigned g_w2h[2][(FDIM/2) * DMODEL];
__device__ unsigned g_w2l[2][(FDIM/2) * DMODEL];
__device__ float g_bqkv[2][QKVW];

// ---- helpers ---------------------------------------------------------------
__device__ __forceinline__ void split_bf16(float x, __nv_bfloat16& h, __nv_bfloat16& l)
{
    h = __float2bfloat16_rn(x);
    l = __float2bfloat16_rn(x - __bfloat162float(h));
}
__device__ __forceinline__ unsigned packb(__nv_bfloat16 a, __nv_bfloat16 b)
{
    __nv_bfloat162 p; p.x = a; p.y = b;       // a = low 16 bits (first element)
    return *(unsigned*)&p;
}
__device__ __forceinline__ void mma_bf16(float* c, const unsigned* a,
                                         unsigned b0, unsigned b1)
{
    asm volatile(
        "mma.sync.aligned.m16n8k16.row.col.f32.bf16.bf16.f32 "
        "{%0,%1,%2,%3}, {%4,%5,%6,%7}, {%8,%9}, {%0,%1,%2,%3};"
        : "+f"(c[0]), "+f"(c[1]), "+f"(c[2]), "+f"(c[3])
        : "r"(a[0]), "r"(a[1]), "r"(a[2]), "r"(a[3]), "r"(b0), "r"(b1));
}
__device__ __forceinline__ void cp16(void* dst, const void* src, bool pred)
{
    unsigned d = (unsigned)__cvta_generic_to_shared(dst);
    int sz = pred ? 16 : 0;
    asm volatile("cp.async.cg.shared.global [%0], [%1], 16, %2;\n"
                 :: "r"(d), "l"(src), "r"(sz));
}
#define CP_COMMIT() asm volatile("cp.async.commit_group;\n")
#define CP_WAIT1()  asm volatile("cp.async.wait_group 1;\n")

// ---------------------------------------------------------------------------
// Conversion kernels
// ---------------------------------------------------------------------------
// activations: fp32 [n4 float4s] -> bf16 hi/lo
__global__ void split_act_kernel(const float* __restrict__ X,
                                 __nv_bfloat16* __restrict__ Hh,
                                 __nv_bfloat16* __restrict__ Hl, int n4)
{
    int i = blockIdx.x * 256 + threadIdx.x;
    if (i >= n4) return;
    float4 v = ((const float4*)X)[i];
    __nv_bfloat16 h0,l0,h1,l1,h2,l2,h3,l3;
    split_bf16(v.x, h0, l0); split_bf16(v.y, h1, l1);
    split_bf16(v.z, h2, l2); split_bf16(v.w, h3, l3);
    uint2 wh, wl;
    wh.x = packb(h0, h1); wh.y = packb(h2, h3);
    wl.x = packb(l0, l1); wl.y = packb(l2, l3);
    ((uint2*)Hh)[i] = wh;
    ((uint2*)Hl)[i] = wl;
}

// weights: fp32 [K][Nsrc] -> k-pair packed uint32 [K/2][Ndst] at column offset
__global__ void pack_w_kernel(const float* __restrict__ W,
                              unsigned* __restrict__ Dh,
                              unsigned* __restrict__ Dl,
                              int Nsrc, int Ndst, int coloff)
{
    int n  = blockIdx.x * 256 + threadIdx.x;
    int kp = blockIdx.y;
    if (n >= Nsrc) return;
    float e = W[(size_t)(2 * kp) * Nsrc + n];
    float o = W[(size_t)(2 * kp + 1) * Nsrc + n];
    __nv_bfloat16 eh, el, oh, ol;
    split_bf16(e, eh, el); split_bf16(o, oh, ol);
    Dh[(size_t)kp * Ndst + coloff + n] = packb(eh, oh);
    Dl[(size_t)kp * Ndst + coloff + n] = packb(el, ol);
}

__global__ void concat3_kernel(const float* __restrict__ a,
                               const float* __restrict__ b,
                               const float* __restrict__ c,
                               float* __restrict__ d)
{
    int i = blockIdx.x * 256 + threadIdx.x;
    if (i < DMODEL)           d[i] = a[i];
    else if (i < 2 * DMODEL)  d[i] = b[i - DMODEL];
    else if (i < 3 * DMODEL)  d[i] = c[i - 2 * DMODEL];
}

// ---------------------------------------------------------------------------
// LayerNorm: one block per row, 256 threads, float4 per thread
// ---------------------------------------------------------------------------
__global__ void ln_kernel(const float* __restrict__ X,
                          const float* __restrict__ sc,
                          const float* __restrict__ bi,
                          float* __restrict__ Y)
{
    int row = blockIdx.x;
    int t   = threadIdx.x;
    const float4* xr = (const float4*)(X + (size_t)row * DMODEL);
    float4 v = xr[t];
    float s  = v.x + v.y + v.z + v.w;
    float ss = v.x*v.x + v.y*v.y + v.z*v.z + v.w*v.w;
    #pragma unroll
    for (int off = 16; off; off >>= 1) {
        s  += __shfl_xor_sync(0xffffffffu, s,  off);
        ss += __shfl_xor_sync(0xffffffffu, ss, off);
    }
    __shared__ float redS[8], redQ[8];
    int w = t >> 5;
    if ((t & 31) == 0) { redS[w] = s; redQ[w] = ss; }
    __syncthreads();
    float S = 0.f, Q = 0.f;
    #pragma unroll
    for (int i = 0; i < 8; i++) { S += redS[i]; Q += redQ[i]; }
    float mean = S * (1.0f / DMODEL);
    float var  = Q * (1.0f / DMODEL) - mean * mean;
    float r    = rsqrtf(var + 1e-5f);
    float4 scv = ((const float4*)sc)[t];
    float4 bv  = ((const float4*)bi)[t];
    float4 o;
    o.x = (v.x - mean) * r * scv.x + bv.x;
    o.y = (v.y - mean) * r * scv.y + bv.y;
    o.z = (v.z - mean) * r * scv.z + bv.z;
    o.w = (v.w - mean) * r * scv.w + bv.w;
    ((float4*)(Y + (size_t)row * DMODEL))[t] = o;
}

// ---------------------------------------------------------------------------
// Pipelined bf16x3 GEMM. A: bf16 hi/lo row-major [M][K]. B: packed k-pair
// uint32 hi/lo [K/2][N]. 128x128 CTA tile, BK=16, 2-stage cp.async pipeline.
// smem: A rows stride 24 bf16 (12 words: conflict-free frag loads);
//       B rows stride 136 words (conflict-free).
// ---------------------------------------------------------------------------
__global__ __launch_bounds__(256, 1)
void gemm_bf16x3_kernel(const __nv_bfloat16* __restrict__ Agh,
                        const __nv_bfloat16* __restrict__ Agl,
                        const unsigned* __restrict__ Bgh,
                        const unsigned* __restrict__ Bgl,
                        const float* __restrict__ bias,
                        const float* __restrict__ res,
                        float* __restrict__ C,
                        int M, int N, int K)
{
    __shared__ __align__(16) __nv_bfloat16 sAh[2][128 * 24];
    __shared__ __align__(16) __nv_bfloat16 sAl[2][128 * 24];
    __shared__ __align__(16) unsigned     sBh[2][8 * 136];
    __shared__ __align__(16) unsigned     sBl[2][8 * 136];

    const int bm = blockIdx.y * 128;
    const int bn = blockIdx.x * 128;
    const int tid  = threadIdx.x;
    const int lane = tid & 31;
    const int wid  = tid >> 5;
    const int wm = (wid >> 2) * 64;
    const int wn = (wid & 3) * 32;
    const int g  = lane >> 2;
    const int qd = lane & 3;

    // per-thread copy coordinates
    const int ar   = tid >> 1;          // 0..127
    const int ahf  = tid & 1;           // 0/1 (8-elem half)
    const int bkp  = tid >> 5;          // 0..7
    const int bc   = tid & 31;          // 0..31 (4-word chunk)
    const bool apred = (bm + ar) < M;

    float acc[4][4][4];
    #pragma unroll
    for (int i = 0; i < 4; i++)
        #pragma unroll
        for (int j = 0; j < 4; j++)
            #pragma unroll
            for (int r = 0; r < 4; r++) acc[i][j][r] = 0.f;

    const int nIter = K >> 4;

    // stage loader
    #define LOAD_STAGE(s, k0)                                                  \
    {                                                                          \
        const __nv_bfloat16* a0 = Agh + (size_t)(bm + ar) * K + (k0) + ahf*8;  \
        const __nv_bfloat16* a1 = Agl + (size_t)(bm + ar) * K + (k0) + ahf*8;  \
        cp16(&sAh[s][ar * 24 + ahf * 8], a0, apred);                           \
        cp16(&sAl[s][ar * 24 + ahf * 8], a1, apred);                           \
        const unsigned* b0 = Bgh + (size_t)(((k0) >> 1) + bkp) * N + bn + bc*4;\
        const unsigned* b1 = Bgl + (size_t)(((k0) >> 1) + bkp) * N + bn + bc*4;\
        cp16(&sBh[s][bkp * 136 + bc * 4], b0, true);                           \
        cp16(&sBl[s][bkp * 136 + bc * 4], b1, true);                           \
    }

    LOAD_STAGE(0, 0);
    CP_COMMIT();

    for (int i = 0; i < nIter; i++) {
        if (i + 1 < nIter) LOAD_STAGE((i + 1) & 1, (i + 1) * 16);
        CP_COMMIT();
        CP_WAIT1();
        __syncthreads();

        const int s = i & 1;
        const unsigned* wAh = (const unsigned*)sAh[s];
        const unsigned* wAl = (const unsigned*)sAl[s];

        unsigned ah[4][4], al[4][4];
        #pragma unroll
        for (int mi = 0; mi < 4; mi++) {
            int ra = (wm + mi * 16 + g) * 12;
            int rb = ra + 8 * 12;
            ah[mi][0] = wAh[ra + qd];     ah[mi][1] = wAh[rb + qd];
            ah[mi][2] = wAh[ra + 4 + qd]; ah[mi][3] = wAh[rb + 4 + qd];
            al[mi][0] = wAl[ra + qd];     al[mi][1] = wAl[rb + qd];
            al[mi][2] = wAl[ra + 4 + qd]; al[mi][3] = wAl[rb + 4 + qd];
        }
        #pragma unroll
        for (int ni = 0; ni < 4; ni++) {
            int n0 = wn + ni * 8 + g;
            unsigned bh0 = sBh[s][qd * 136 + n0];
            unsigned bh1 = sBh[s][(4 + qd) * 136 + n0];
            unsigned bl0 = sBl[s][qd * 136 + n0];
            unsigned bl1 = sBl[s][(4 + qd) * 136 + n0];
            #pragma unroll
            for (int mi = 0; mi < 4; mi++) {
                mma_bf16(acc[mi][ni], ah[mi], bh0, bh1);
                mma_bf16(acc[mi][ni], ah[mi], bl0, bl1);
                mma_bf16(acc[mi][ni], al[mi], bh0, bh1);
            }
        }
        __syncthreads();
    }

    // epilogue
    #pragma unroll
    for (int mi = 0; mi < 4; mi++) {
        #pragma unroll
        for (int ni = 0; ni < 4; ni++) {
            int r0 = bm + wm + mi * 16 + g;
            int cc = bn + wn + ni * 8 + qd * 2;
            float2 bb = *(const float2*)&bias[cc];
            if (r0 < M) {
                float2 o;
                o.x = acc[mi][ni][0] + bb.x;
                o.y = acc[mi][ni][1] + bb.y;
                if (res) {
                    float2 rr = *(const float2*)&res[(size_t)r0 * N + cc];
                    o.x += rr.x; o.y += rr.y;
                }
                *(float2*)&C[(size_t)r0 * N + cc] = o;
            }
            int r1 = r0 + 8;
            if (r1 < M) {
                float2 o;
                o.x = acc[mi][ni][2] + bb.x;
                o.y = acc[mi][ni][3] + bb.y;
                if (res) {
                    float2 rr = *(const float2*)&res[(size_t)r1 * N + cc];
                    o.x += rr.x; o.y += rr.y;
                }
                *(float2*)&C[(size_t)r1 * N + cc] = o;
            }
        }
    }
    #undef LOAD_STAGE
}

// ---------------------------------------------------------------------------
// Attention: warp-per-query, key-parallel lanes. 512 threads (16 warps).
// smem: Kt (transposed, float2 per (d-pair, key)) + V (row-major).
// Query/Key/Value read from fused qkv buffer (stride 3072).
// ---------------------------------------------------------------------------
__global__ __launch_bounds__(512, 1)
void attn_kernel(const float* __restrict__ qkv,
                 const float* __restrict__ Hh,
                 float* __restrict__ O)
{
    int ci = blockIdx.x;   // chunk
    int hh = blockIdx.y;   // head
    int b  = blockIdx.z;   // batch

    extern __shared__ float sm[];
    float2* Kt2 = (float2*)sm;          // [32 d-pairs][288 keys]
    float*  Vs  = sm + 18432;           // [288 keys][64]

    int nkr   = (ci < 7) ? 32 : 0;
    int body0 = (ci >= 1) ? 128 * (ci - 1) : 0;
    int nk    = nkr + (128 * (ci + 1) - body0);   // 160 / 288 / 256
    int nq    = (ci < 7) ? 160 : 128;
    int base  = b * TTOT;
    int tid   = threadIdx.x;

    // ---- stage K transposed --------------------------------------------------
    if (tid < nk) {
        int key  = tid;
        int krow = (key < nkr) ? (32 * ci + key) : (NRIGHT + body0 + (key - nkr));
        const float4* kp4 = (const float4*)&qkv[(size_t)(base + krow) * QKVW + DMODEL + hh * DK];
        #pragma unroll
        for (int d4 = 0; d4 < 16; d4++) {
            float4 v = kp4[d4];
            Kt2[(2 * d4) * 288 + key]     = make_float2(v.x, v.y);
            Kt2[(2 * d4 + 1) * 288 + key] = make_float2(v.z, v.w);
        }
    }
    // ---- stage V row-major ---------------------------------------------------
    for (int idx = tid; idx < nk * 16; idx += 512) {
        int key = idx >> 4;
        int d4  = idx & 15;
        int krow = (key < nkr) ? (32 * ci + key) : (NRIGHT + body0 + (key - nkr));
        float4 v = *(const float4*)&qkv[(size_t)(base + krow) * QKVW + 2 * DMODEL + hh * DK + d4 * 4];
        *(float4*)&Vs[key * 64 + d4 * 4] = v;
    }
    __syncthreads();

    int warp = tid >> 5;
    int lane = tid & 31;

    for (int qi = warp; qi < nq; qi += 16) {
        int qrow;
        if (ci < 7) qrow = (qi < 32) ? (32 * ci + qi) : (NRIGHT + 128 * ci + qi - 32);
        else        qrow = NRIGHT + 128 * 7 + qi;

        const float4* qp = (const float4*)&qkv[(size_t)(base + qrow) * QKVW + hh * DK];
        float q[64];
        #pragma unroll
        for (int d4 = 0; d4 < 16; d4++) {
            float4 t = qp[d4];
            q[4*d4+0] = t.x * 0.125f;
            q[4*d4+1] = t.y * 0.125f;
            q[4*d4+2] = t.z * 0.125f;
            q[4*d4+3] = t.w * 0.125f;
        }

        float m = -1e30f, l = 0.f, o0 = 0.f, o1 = 0.f;

        for (int j0 = 0; j0 < nk; j0 += 32) {
            int key = j0 + lane;
            float s = 0.f;
            #pragma unroll
            for (int d2 = 0; d2 < 32; d2++) {
                float2 kk = Kt2[d2 * 288 + key];
                s += q[2*d2] * kk.x + q[2*d2+1] * kk.y;
            }
            float mb = s;
            #pragma unroll
            for (int off = 16; off; off >>= 1)
                mb = fmaxf(mb, __shfl_xor_sync(0xffffffffu, mb, off));
            float mnew = fmaxf(m, mb);
            float c = __expf(m - mnew);
            float p = __expf(s - mnew);
            float ps = p;
            #pragma unroll
            for (int off = 16; off; off >>= 1)
                ps += __shfl_xor_sync(0xffffffffu, ps, off);
            l = l * c + ps;
            o0 *= c; o1 *= c;
            m = mnew;
            const float2* vb = (const float2*)&Vs[j0 * 64];
            #pragma unroll
            for (int jj = 0; jj < 32; jj++) {
                float pj = __shfl_sync(0xffffffffu, p, jj);
                float2 vv = vb[jj * 32 + lane];
                o0 += pj * vv.x;
                o1 += pj * vv.y;
            }
        }

        float inv = 1.0f / l;
        size_t ooff = (size_t)(base + qrow) * DMODEL + hh * DK + 2 * lane;
        float2 hv = *(const float2*)&Hh[ooff];
        float2 out;
        out.x = o0 * inv + hv.x;
        out.y = o1 * inv + hv.y;
        *(float2*)&O[ooff] = out;
    }
}

// ---------------------------------------------------------------------------
extern "C" void kernel_launch(void* const* d_in, const int* in_sizes, int n_in,
                              void* d_out, int out_size)
{
    const float* input       = (const float*)d_in[0];
    const float* ln_in_scale = (const float*)d_in[1];
    const float* ln_in_bias  = (const float*)d_in[2];
    const float* Wq          = (const float*)d_in[3];
    const float* bq          = (const float*)d_in[4];
    const float* Wk          = (const float*)d_in[5];
    const float* bk          = (const float*)d_in[6];
    const float* Wv          = (const float*)d_in[7];
    const float* bv          = (const float*)d_in[8];
    const float* ln1_scale   = (const float*)d_in[9];
    const float* ln1_bias    = (const float*)d_in[10];
    const float* W1          = (const float*)d_in[11];
    const float* b1          = (const float*)d_in[12];
    const float* W2          = (const float*)d_in[13];
    const float* b2          = (const float*)d_in[14];
    const float* ln2_scale   = (const float*)d_in[15];
    const float* ln2_bias    = (const float*)d_in[16];
    // d_in[17] = mask: unused (analytic)

    float *h, *attn, *y1, *y2, *xb, *qkv, *bqkv;
    __nv_bfloat16 *ah, *al;
    unsigned *wqkvh, *wqkvl, *w1h, *w1l, *w2h, *w2l;
    cudaGetSymbolAddress((void**)&h,     g_h);
    cudaGetSymbolAddress((void**)&attn,  g_attn);
    cudaGetSymbolAddress((void**)&y1,    g_y1);
    cudaGetSymbolAddress((void**)&y2,    g_y2);
    cudaGetSymbolAddress((void**)&xb,    g_x);
    cudaGetSymbolAddress((void**)&qkv,   g_qkv);
    cudaGetSymbolAddress((void**)&ah,    g_ah);
    cudaGetSymbolAddress((void**)&al,    g_al);
    cudaGetSymbolAddress((void**)&wqkvh, g_wqkvh);
    cudaGetSymbolAddress((void**)&wqkvl, g_wqkvl);
    cudaGetSymbolAddress((void**)&w1h,   g_w1h);
    cudaGetSymbolAddress((void**)&w1l,   g_w1l);
    cudaGetSymbolAddress((void**)&w2h,   g_w2h);
    cudaGetSymbolAddress((void**)&w2l,   g_w2l);
    cudaGetSymbolAddress((void**)&bqkv,  g_bqkv);

    cudaFuncSetAttribute(attn_kernel,
                         cudaFuncAttributeMaxDynamicSharedMemorySize, 147456);

    const int M = MROWS;
    const size_t WQKV_SZ = (size_t)(DMODEL/2) * QKVW;
    const size_t W1_SZ   = (size_t)(DMODEL/2) * FDIM;
    const size_t W2_SZ   = (size_t)(FDIM/2) * DMODEL;

    // ---- weight packing (both layers, upfront) -----------------------------
    for (int l = 0; l < 2; l++) {
        size_t oD  = (size_t)l * DMODEL;
        size_t oDD = (size_t)l * DMODEL * DMODEL;
        size_t oDF = (size_t)l * DMODEL * FDIM;
        dim3 gq(DMODEL / 256, DMODEL / 2);
        pack_w_kernel<<<gq, 256>>>(Wq + oDD, wqkvh + l * WQKV_SZ, wqkvl + l * WQKV_SZ,
                                   DMODEL, QKVW, 0);
        pack_w_kernel<<<gq, 256>>>(Wk + oDD, wqkvh + l * WQKV_SZ, wqkvl + l * WQKV_SZ,
                                   DMODEL, QKVW, DMODEL);
        pack_w_kernel<<<gq, 256>>>(Wv + oDD, wqkvh + l * WQKV_SZ, wqkvl + l * WQKV_SZ,
                                   DMODEL, QKVW, 2 * DMODEL);
        dim3 g1(FDIM / 256, DMODEL / 2);
        pack_w_kernel<<<g1, 256>>>(W1 + oDF, w1h + l * W1_SZ, w1l + l * W1_SZ,
                                   FDIM, FDIM, 0);
        dim3 g2(DMODEL / 256, FDIM / 2);
        pack_w_kernel<<<g2, 256>>>(W2 + oDF, w2h + l * W2_SZ, w2l + l * W2_SZ,
                                   DMODEL, DMODEL, 0);
        concat3_kernel<<<QKVW / 256, 256>>>(bq + oD, bk + oD, bv + oD, bqkv + l * QKVW);
    }

    dim3 gQKV(QKVW / 128,  (M + 127) / 128);   // (24, 20)
    dim3 gF  (FDIM / 128,  (M + 127) / 128);   // (32, 20)
    dim3 gD  (DMODEL / 128,(M + 127) / 128);   // (8, 20)
    dim3 attnGrid(8, NHEAD, BATCH);

    const int n4D = M * DMODEL / 4;
    const int n4F = M * FDIM / 4;

    const float* x = input;
    for (int l = 0; l < 2; l++) {
        size_t oD = (size_t)l * DMODEL;
        size_t oF = (size_t)l * FDIM;

        // LN_in -> h; split
        ln_kernel<<<M, 256>>>(x, ln_in_scale + oD, ln_in_bias + oD, h);
        split_act_kernel<<<(n4D + 255) / 256, 256>>>(h, ah, al, n4D);

        // fused QKV GEMM
        gemm_bf16x3_kernel<<<gQKV, 256>>>(ah, al,
            wqkvh + l * WQKV_SZ, wqkvl + l * WQKV_SZ,
            bqkv + l * QKVW, nullptr, qkv, M, QKVW, DMODEL);

        // attention (+h residual)
        attn_kernel<<<attnGrid, 512, 147456>>>(qkv, h, attn);

        // LN1 -> h; split
        ln_kernel<<<M, 256>>>(attn, ln1_scale + oD, ln1_bias + oD, h);
        split_act_kernel<<<(n4D + 255) / 256, 256>>>(h, ah, al, n4D);

        // FFN
        gemm_bf16x3_kernel<<<gF, 256>>>(ah, al,
            w1h + l * W1_SZ, w1l + l * W1_SZ,
            b1 + oF, nullptr, y1, M, FDIM, DMODEL);

        split_act_kernel<<<(n4F + 255) / 256, 256>>>(y1, ah, al, n4F);

        gemm_bf16x3_kernel<<<gD, 256>>>(ah, al,
            w2h + l * W2_SZ, w2l + l * W2_SZ,
            b2 + oD, attn, y2, M, DMODEL, FDIM);

        // LN2
        float* dst = (l == 0) ? xb : (float*)d_out;
        ln_kernel<<<M, 256>>>(y2, ln2_scale + oD, ln2_bias + oD, dst);
        x = xb;
    }
}

// round 5
// speedup vs baseline: 1.1900x; 1.1900x over previous
#include <cuda_runtime.h>
#include <cuda_bf16.h>
#include <math.h>

// ---------------------------------------------------------------------------
// EmformerEncoder  B=2, T=1248, D=1024, H=16, DK=64, F=4096, L=2.
// Analytic block-sparse mask (CHUNK=128, LEFT=128, RIGHT=32).
// Round 5: round-4 design with the ah/al aliasing bug fixed (y1 gets its own
//          hi/lo buffers). Fused LN+split, GEMM epilogue split, merged weight
//          packing, 2 CTAs/SM pipelined bf16x3 HMMA GEMM.
// ---------------------------------------------------------------------------

#define TTOT   1248
#define NRIGHT 224
#define BATCH  2
#define MROWS  (BATCH * TTOT)   // 2496
#define DMODEL 1024
#define NHEAD  16
#define DK     64
#define FDIM   4096
#define QKVW   3072

// ---- scratch (device globals) ---------------------------------------------
__device__ float g_h[MROWS * DMODEL];     // LN_in fp32 (attn residual)
__device__ float g_attn[MROWS * DMODEL];
__device__ float g_y2[MROWS * DMODEL];
__device__ float g_x[MROWS * DMODEL];
__device__ float g_qkv[MROWS * QKVW];
__device__ __nv_bfloat16 g_ah[MROWS * DMODEL];  // LN split out
__device__ __nv_bfloat16 g_al[MROWS * DMODEL];
__device__ __nv_bfloat16 g_y1h[MROWS * FDIM];   // W1 GEMM split out
__device__ __nv_bfloat16 g_y1l[MROWS * FDIM];
__device__ unsigned g_wqkvh[2][(DMODEL/2) * QKVW];
__device__ unsigned g_wqkvl[2][(DMODEL/2) * QKVW];
__device__ unsigned g_w1h[2][(DMODEL/2) * FDIM];
__device__ unsigned g_w1l[2][(DMODEL/2) * FDIM];
__device__ unsigned g_w2h[2][(FDIM/2) * DMODEL];
__device__ unsigned g_w2l[2][(FDIM/2) * DMODEL];
__device__ float g_bqkv[2][QKVW];

// ---- helpers ---------------------------------------------------------------
__device__ __forceinline__ void split_bf16(float x, __nv_bfloat16& h, __nv_bfloat16& l)
{
    h = __float2bfloat16_rn(x);
    l = __float2bfloat16_rn(x - __bfloat162float(h));
}
__device__ __forceinline__ unsigned packb(__nv_bfloat16 a, __nv_bfloat16 b)
{
    __nv_bfloat162 p; p.x = a; p.y = b;
    return *(unsigned*)&p;
}
__device__ __forceinline__ void mma_bf16(float* c, const unsigned* a,
                                         unsigned b0, unsigned b1)
{
    asm volatile(
        "mma.sync.aligned.m16n8k16.row.col.f32.bf16.bf16.f32 "
        "{%0,%1,%2,%3}, {%4,%5,%6,%7}, {%8,%9}, {%0,%1,%2,%3};"
        : "+f"(c[0]), "+f"(c[1]), "+f"(c[2]), "+f"(c[3])
        : "r"(a[0]), "r"(a[1]), "r"(a[2]), "r"(a[3]), "r"(b0), "r"(b1));
}
__device__ __forceinline__ void cp16(void* dst, const void* src, bool pred)
{
    unsigned d = (unsigned)__cvta_generic_to_shared(dst);
    int sz = pred ? 16 : 0;
    asm volatile("cp.async.cg.shared.global [%0], [%1], 16, %2;\n"
                 :: "r"(d), "l"(src), "r"(sz));
}
#define CP_COMMIT() asm volatile("cp.async.commit_group;\n")
#define CP_WAIT1()  asm volatile("cp.async.wait_group 1;\n")

// ---------------------------------------------------------------------------
// Weight packing: one launch per weight class, both layers via grid.z.
// Output: k-pair packed uint32 hi/lo [K/2][N].
// ---------------------------------------------------------------------------
__global__ void pack_qkv_kernel(const float* __restrict__ Wq,
                                const float* __restrict__ Wk,
                                const float* __restrict__ Wv,
                                unsigned* __restrict__ Dh,
                                unsigned* __restrict__ Dl)
{
    int n  = blockIdx.x * 256 + threadIdx.x;     // 0..3071
    int kp = blockIdx.y;                          // 0..511
    int l  = blockIdx.z;
    const float* W = (n < DMODEL) ? Wq : (n < 2 * DMODEL) ? Wk : Wv;
    int nc = n & (DMODEL - 1);
    W += (size_t)l * DMODEL * DMODEL;
    float e = W[(size_t)(2 * kp) * DMODEL + nc];
    float o = W[(size_t)(2 * kp + 1) * DMODEL + nc];
    __nv_bfloat16 eh, el, oh, ol;
    split_bf16(e, eh, el); split_bf16(o, oh, ol);
    size_t idx = (size_t)l * (DMODEL/2) * QKVW + (size_t)kp * QKVW + n;
    Dh[idx] = packb(eh, oh);
    Dl[idx] = packb(el, ol);
}

__global__ void pack_w_kernel(const float* __restrict__ W,
                              unsigned* __restrict__ Dh,
                              unsigned* __restrict__ Dl,
                              int N, int Khalf)
{
    int n  = blockIdx.x * 256 + threadIdx.x;
    int kp = blockIdx.y;
    int l  = blockIdx.z;
    W += (size_t)l * (2 * (size_t)Khalf) * N;
    float e = W[(size_t)(2 * kp) * N + n];
    float o = W[(size_t)(2 * kp + 1) * N + n];
    __nv_bfloat16 eh, el, oh, ol;
    split_bf16(e, eh, el); split_bf16(o, oh, ol);
    size_t idx = (size_t)l * Khalf * N + (size_t)kp * N + n;
    Dh[idx] = packb(eh, oh);
    Dl[idx] = packb(el, ol);
}

__global__ void concat3_kernel(const float* __restrict__ a,
                               const float* __restrict__ b,
                               const float* __restrict__ c,
                               float* __restrict__ d)
{
    int i = blockIdx.x * 256 + threadIdx.x;
    int l = blockIdx.y;
    const float* s = (i < DMODEL) ? a : (i < 2 * DMODEL) ? b : c;
    d[(size_t)l * QKVW + i] = s[(size_t)l * DMODEL + (i & (DMODEL - 1))];
}

// ---------------------------------------------------------------------------
// LayerNorm + optional fp32 out + optional bf16 hi/lo split out.
// ---------------------------------------------------------------------------
__global__ void ln_kernel(const float* __restrict__ X,
                          const float* __restrict__ sc,
                          const float* __restrict__ bi,
                          float* __restrict__ Yf,
                          __nv_bfloat16* __restrict__ Yh,
                          __nv_bfloat16* __restrict__ Yl)
{
    int row = blockIdx.x;
    int t   = threadIdx.x;
    const float4* xr = (const float4*)(X + (size_t)row * DMODEL);
    float4 v = xr[t];
    float s  = v.x + v.y + v.z + v.w;
    float ss = v.x*v.x + v.y*v.y + v.z*v.z + v.w*v.w;
    #pragma unroll
    for (int off = 16; off; off >>= 1) {
        s  += __shfl_xor_sync(0xffffffffu, s,  off);
        ss += __shfl_xor_sync(0xffffffffu, ss, off);
    }
    __shared__ float redS[8], redQ[8];
    int w = t >> 5;
    if ((t & 31) == 0) { redS[w] = s; redQ[w] = ss; }
    __syncthreads();
    float S = 0.f, Q = 0.f;
    #pragma unroll
    for (int i = 0; i < 8; i++) { S += redS[i]; Q += redQ[i]; }
    float mean = S * (1.0f / DMODEL);
    float var  = Q * (1.0f / DMODEL) - mean * mean;
    float r    = rsqrtf(var + 1e-5f);
    float4 scv = ((const float4*)sc)[t];
    float4 bv  = ((const float4*)bi)[t];
    float4 o;
    o.x = (v.x - mean) * r * scv.x + bv.x;
    o.y = (v.y - mean) * r * scv.y + bv.y;
    o.z = (v.z - mean) * r * scv.z + bv.z;
    o.w = (v.w - mean) * r * scv.w + bv.w;
    size_t base = (size_t)row * DMODEL;
    if (Yf) ((float4*)(Yf + base))[t] = o;
    if (Yh) {
        __nv_bfloat16 h0,l0,h1,l1,h2,l2,h3,l3;
        split_bf16(o.x, h0, l0); split_bf16(o.y, h1, l1);
        split_bf16(o.z, h2, l2); split_bf16(o.w, h3, l3);
        uint2 wh, wl;
        wh.x = packb(h0, h1); wh.y = packb(h2, h3);
        wl.x = packb(l0, l1); wl.y = packb(l2, l3);
        ((uint2*)(Yh + base))[t] = wh;
        ((uint2*)(Yl + base))[t] = wl;
    }
}

// ---------------------------------------------------------------------------
// Pipelined bf16x3 GEMM. A: bf16 hi/lo row-major [M][K]. B: packed k-pair
// uint32 hi/lo [K/2][N]. 128x128 CTA tile, BK=16, 2-stage cp.async pipeline,
// 2 CTAs/SM. Epilogue: fp32 C (+res) OR bf16 hi/lo split output.
// ---------------------------------------------------------------------------
__global__ __launch_bounds__(256, 2)
void gemm_bf16x3_kernel(const __nv_bfloat16* __restrict__ Agh,
                        const __nv_bfloat16* __restrict__ Agl,
                        const unsigned* __restrict__ Bgh,
                        const unsigned* __restrict__ Bgl,
                        const float* __restrict__ bias,
                        const float* __restrict__ res,
                        float* __restrict__ C,
                        __nv_bfloat16* __restrict__ Ch,
                        __nv_bfloat16* __restrict__ Cl,
                        int M, int N, int K)
{
    __shared__ __align__(16) __nv_bfloat16 sAh[2][128 * 24];
    __shared__ __align__(16) __nv_bfloat16 sAl[2][128 * 24];
    __shared__ __align__(16) unsigned     sBh[2][8 * 136];
    __shared__ __align__(16) unsigned     sBl[2][8 * 136];

    const int bm = blockIdx.y * 128;
    const int bn = blockIdx.x * 128;
    const int tid  = threadIdx.x;
    const int lane = tid & 31;
    const int wid  = tid >> 5;
    const int wm = (wid >> 2) * 64;
    const int wn = (wid & 3) * 32;
    const int g  = lane >> 2;
    const int qd = lane & 3;

    const int ar   = tid >> 1;
    const int ahf  = tid & 1;
    const int bkp  = tid >> 5;
    const int bc   = tid & 31;
    const bool apred = (bm + ar) < M;

    float acc[4][4][4];
    #pragma unroll
    for (int i = 0; i < 4; i++)
        #pragma unroll
        for (int j = 0; j < 4; j++)
            #pragma unroll
            for (int r = 0; r < 4; r++) acc[i][j][r] = 0.f;

    const int nIter = K >> 4;

    #define LOAD_STAGE(s, k0)                                                  \
    {                                                                          \
        const __nv_bfloat16* a0 = Agh + (size_t)(bm + ar) * K + (k0) + ahf*8;  \
        const __nv_bfloat16* a1 = Agl + (size_t)(bm + ar) * K + (k0) + ahf*8;  \
        cp16(&sAh[s][ar * 24 + ahf * 8], a0, apred);                           \
        cp16(&sAl[s][ar * 24 + ahf * 8], a1, apred);                           \
        const unsigned* b0 = Bgh + (size_t)(((k0) >> 1) + bkp) * N + bn + bc*4;\
        const unsigned* b1 = Bgl + (size_t)(((k0) >> 1) + bkp) * N + bn + bc*4;\
        cp16(&sBh[s][bkp * 136 + bc * 4], b0, true);                           \
        cp16(&sBl[s][bkp * 136 + bc * 4], b1, true);                           \
    }

    LOAD_STAGE(0, 0);
    CP_COMMIT();

    for (int i = 0; i < nIter; i++) {
        if (i + 1 < nIter) LOAD_STAGE((i + 1) & 1, (i + 1) * 16);
        CP_COMMIT();
        CP_WAIT1();
        __syncthreads();

        const int s = i & 1;
        const unsigned* wAh = (const unsigned*)sAh[s];
        const unsigned* wAl = (const unsigned*)sAl[s];

        unsigned ah[4][4], al[4][4];
        #pragma unroll
        for (int mi = 0; mi < 4; mi++) {
            int ra = (wm + mi * 16 + g) * 12;
            int rb = ra + 8 * 12;
            ah[mi][0] = wAh[ra + qd];     ah[mi][1] = wAh[rb + qd];
            ah[mi][2] = wAh[ra + 4 + qd]; ah[mi][3] = wAh[rb + 4 + qd];
            al[mi][0] = wAl[ra + qd];     al[mi][1] = wAl[rb + qd];
            al[mi][2] = wAl[ra + 4 + qd]; al[mi][3] = wAl[rb + 4 + qd];
        }
        #pragma unroll
        for (int ni = 0; ni < 4; ni++) {
            int n0 = wn + ni * 8 + g;
            unsigned bh0 = sBh[s][qd * 136 + n0];
            unsigned bh1 = sBh[s][(4 + qd) * 136 + n0];
            unsigned bl0 = sBl[s][qd * 136 + n0];
            unsigned bl1 = sBl[s][(4 + qd) * 136 + n0];
            #pragma unroll
            for (int mi = 0; mi < 4; mi++) {
                mma_bf16(acc[mi][ni], ah[mi], bh0, bh1);
                mma_bf16(acc[mi][ni], ah[mi], bl0, bl1);
                mma_bf16(acc[mi][ni], al[mi], bh0, bh1);
            }
        }
        __syncthreads();
    }
    #undef LOAD_STAGE

    // epilogue
    #pragma unroll
    for (int mi = 0; mi < 4; mi++) {
        #pragma unroll
        for (int ni = 0; ni < 4; ni++) {
            #pragma unroll
            for (int half = 0; half < 2; half++) {
                int row = bm + wm + mi * 16 + g + half * 8;
                if (row >= M) continue;
                int cc = bn + wn + ni * 8 + qd * 2;
                float2 bb = *(const float2*)&bias[cc];
                float ox = acc[mi][ni][2 * half + 0] + bb.x;
                float oy = acc[mi][ni][2 * half + 1] + bb.y;
                if (Ch) {
                    __nv_bfloat16 hx, lx, hy, ly;
                    split_bf16(ox, hx, lx);
                    split_bf16(oy, hy, ly);
                    size_t wi = ((size_t)row * N + cc) >> 1;
                    ((unsigned*)Ch)[wi] = packb(hx, hy);
                    ((unsigned*)Cl)[wi] = packb(lx, ly);
                } else {
                    if (res) {
                        float2 rr = *(const float2*)&res[(size_t)row * N + cc];
                        ox += rr.x; oy += rr.y;
                    }
                    float2 o; o.x = ox; o.y = oy;
                    *(float2*)&C[(size_t)row * N + cc] = o;
                }
            }
        }
    }
}

// ---------------------------------------------------------------------------
// Attention: warp-per-query, key-parallel lanes. 512 threads (16 warps).
// ---------------------------------------------------------------------------
__global__ __launch_bounds__(512, 1)
void attn_kernel(const float* __restrict__ qkv,
                 const float* __restrict__ Hh,
                 float* __restrict__ O)
{
    int ci = blockIdx.x;
    int hh = blockIdx.y;
    int b  = blockIdx.z;

    extern __shared__ float sm[];
    float2* Kt2 = (float2*)sm;          // [32 d-pairs][288 keys]
    float*  Vs  = sm + 18432;           // [288 keys][64]

    int nkr   = (ci < 7) ? 32 : 0;
    int body0 = (ci >= 1) ? 128 * (ci - 1) : 0;
    int nk    = nkr + (128 * (ci + 1) - body0);
    int nq    = (ci < 7) ? 160 : 128;
    int base  = b * TTOT;
    int tid   = threadIdx.x;

    if (tid < nk) {
        int key  = tid;
        int krow = (key < nkr) ? (32 * ci + key) : (NRIGHT + body0 + (key - nkr));
        const float4* kp4 = (const float4*)&qkv[(size_t)(base + krow) * QKVW + DMODEL + hh * DK];
        #pragma unroll
        for (int d4 = 0; d4 < 16; d4++) {
            float4 v = kp4[d4];
            Kt2[(2 * d4) * 288 + key]     = make_float2(v.x, v.y);
            Kt2[(2 * d4 + 1) * 288 + key] = make_float2(v.z, v.w);
        }
    }
    for (int idx = tid; idx < nk * 16; idx += 512) {
        int key = idx >> 4;
        int d4  = idx & 15;
        int krow = (key < nkr) ? (32 * ci + key) : (NRIGHT + body0 + (key - nkr));
        float4 v = *(const float4*)&qkv[(size_t)(base + krow) * QKVW + 2 * DMODEL + hh * DK + d4 * 4];
        *(float4*)&Vs[key * 64 + d4 * 4] = v;
    }
    __syncthreads();

    int warp = tid >> 5;
    int lane = tid & 31;

    for (int qi = warp; qi < nq; qi += 16) {
        int qrow;
        if (ci < 7) qrow = (qi < 32) ? (32 * ci + qi) : (NRIGHT + 128 * ci + qi - 32);
        else        qrow = NRIGHT + 128 * 7 + qi;

        const float4* qp = (const float4*)&qkv[(size_t)(base + qrow) * QKVW + hh * DK];
        float q[64];
        #pragma unroll
        for (int d4 = 0; d4 < 16; d4++) {
            float4 t = qp[d4];
            q[4*d4+0] = t.x * 0.125f;
            q[4*d4+1] = t.y * 0.125f;
            q[4*d4+2] = t.z * 0.125f;
            q[4*d4+3] = t.w * 0.125f;
        }

        float m = -1e30f, l = 0.f, o0 = 0.f, o1 = 0.f;

        for (int j0 = 0; j0 < nk; j0 += 32) {
            int key = j0 + lane;
            float s = 0.f;
            #pragma unroll
            for (int d2 = 0; d2 < 32; d2++) {
                float2 kk = Kt2[d2 * 288 + key];
                s += q[2*d2] * kk.x + q[2*d2+1] * kk.y;
            }
            float mb = s;
            #pragma unroll
            for (int off = 16; off; off >>= 1)
                mb = fmaxf(mb, __shfl_xor_sync(0xffffffffu, mb, off));
            float mnew = fmaxf(m, mb);
            float c = __expf(m - mnew);
            float p = __expf(s - mnew);
            float ps = p;
            #pragma unroll
            for (int off = 16; off; off >>= 1)
                ps += __shfl_xor_sync(0xffffffffu, ps, off);
            l = l * c + ps;
            o0 *= c; o1 *= c;
            m = mnew;
            const float2* vb = (const float2*)&Vs[j0 * 64];
            #pragma unroll
            for (int jj = 0; jj < 32; jj++) {
                float pj = __shfl_sync(0xffffffffu, p, jj);
                float2 vv = vb[jj * 32 + lane];
                o0 += pj * vv.x;
                o1 += pj * vv.y;
            }
        }

        float inv = 1.0f / l;
        size_t ooff = (size_t)(base + qrow) * DMODEL + hh * DK + 2 * lane;
        float2 hv = *(const float2*)&Hh[ooff];
        float2 out;
        out.x = o0 * inv + hv.x;
        out.y = o1 * inv + hv.y;
        *(float2*)&O[ooff] = out;
    }
}

// ---------------------------------------------------------------------------
extern "C" void kernel_launch(void* const* d_in, const int* in_sizes, int n_in,
                              void* d_out, int out_size)
{
    const float* input       = (const float*)d_in[0];
    const float* ln_in_scale = (const float*)d_in[1];
    const float* ln_in_bias  = (const float*)d_in[2];
    const float* Wq          = (const float*)d_in[3];
    const float* bq          = (const float*)d_in[4];
    const float* Wk          = (const float*)d_in[5];
    const float* bk          = (const float*)d_in[6];
    const float* Wv          = (const float*)d_in[7];
    const float* bv          = (const float*)d_in[8];
    const float* ln1_scale   = (const float*)d_in[9];
    const float* ln1_bias    = (const float*)d_in[10];
    const float* W1          = (const float*)d_in[11];
    const float* b1          = (const float*)d_in[12];
    const float* W2          = (const float*)d_in[13];
    const float* b2          = (const float*)d_in[14];
    const float* ln2_scale   = (const float*)d_in[15];
    const float* ln2_bias    = (const float*)d_in[16];
    // d_in[17] = mask: unused (analytic)

    float *h, *attn, *y2, *xb, *qkv, *bqkv;
    __nv_bfloat16 *ah, *al, *y1h, *y1l;
    unsigned *wqkvh, *wqkvl, *w1h, *w1l, *w2h, *w2l;
    cudaGetSymbolAddress((void**)&h,     g_h);
    cudaGetSymbolAddress((void**)&attn,  g_attn);
    cudaGetSymbolAddress((void**)&y2,    g_y2);
    cudaGetSymbolAddress((void**)&xb,    g_x);
    cudaGetSymbolAddress((void**)&qkv,   g_qkv);
    cudaGetSymbolAddress((void**)&ah,    g_ah);
    cudaGetSymbolAddress((void**)&al,    g_al);
    cudaGetSymbolAddress((void**)&y1h,   g_y1h);
    cudaGetSymbolAddress((void**)&y1l,   g_y1l);
    cudaGetSymbolAddress((void**)&wqkvh, g_wqkvh);
    cudaGetSymbolAddress((void**)&wqkvl, g_wqkvl);
    cudaGetSymbolAddress((void**)&w1h,   g_w1h);
    cudaGetSymbolAddress((void**)&w1l,   g_w1l);
    cudaGetSymbolAddress((void**)&w2h,   g_w2h);
    cudaGetSymbolAddress((void**)&w2l,   g_w2l);
    cudaGetSymbolAddress((void**)&bqkv,  g_bqkv);

    cudaFuncSetAttribute(attn_kernel,
                         cudaFuncAttributeMaxDynamicSharedMemorySize, 147456);

    const int M = MROWS;
    const size_t WQKV_SZ = (size_t)(DMODEL/2) * QKVW;
    const size_t W1_SZ   = (size_t)(DMODEL/2) * FDIM;
    const size_t W2_SZ   = (size_t)(FDIM/2) * DMODEL;

    // ---- weight packing: 3 launches + bias concat (both layers each) -------
    {
        dim3 gq(QKVW / 256, DMODEL / 2, 2);
        pack_qkv_kernel<<<gq, 256>>>(Wq, Wk, Wv, wqkvh, wqkvl);
        dim3 g1(FDIM / 256, DMODEL / 2, 2);
        pack_w_kernel<<<g1, 256>>>(W1, w1h, w1l, FDIM, DMODEL / 2);
        dim3 g2(DMODEL / 256, FDIM / 2, 2);
        pack_w_kernel<<<g2, 256>>>(W2, w2h, w2l, DMODEL, FDIM / 2);
        dim3 gc(QKVW / 256, 2);
        concat3_kernel<<<gc, 256>>>(bq, bk, bv, bqkv);
    }

    dim3 gQKV(QKVW / 128,  (M + 127) / 128);   // (24, 20)
    dim3 gF  (FDIM / 128,  (M + 127) / 128);   // (32, 20)
    dim3 gD  (DMODEL / 128,(M + 127) / 128);   // (8, 20)
    dim3 attnGrid(8, NHEAD, BATCH);

    const float* x = input;
    for (int l = 0; l < 2; l++) {
        size_t oD = (size_t)l * DMODEL;
        size_t oF = (size_t)l * FDIM;

        // LN_in: fp32 h (attn residual) + bf16 split for QKV GEMM
        ln_kernel<<<M, 256>>>(x, ln_in_scale + oD, ln_in_bias + oD, h, ah, al);

        // fused QKV GEMM (fp32 out)
        gemm_bf16x3_kernel<<<gQKV, 256>>>(ah, al,
            wqkvh + l * WQKV_SZ, wqkvl + l * WQKV_SZ,
            bqkv + l * QKVW, nullptr, qkv, nullptr, nullptr, M, QKVW, DMODEL);

        // attention (+h residual)
        attn_kernel<<<attnGrid, 512, 147456>>>(qkv, h, attn);

        // LN1: bf16 split only (feeds W1 GEMM)
        ln_kernel<<<M, 256>>>(attn, ln1_scale + oD, ln1_bias + oD,
                              nullptr, ah, al);

        // W1 GEMM -> bf16 hi/lo y1 (separate buffers; NO aliasing with A)
        gemm_bf16x3_kernel<<<gF, 256>>>(ah, al,
            w1h + l * W1_SZ, w1l + l * W1_SZ,
            b1 + oF, nullptr, nullptr, y1h, y1l, M, FDIM, DMODEL);

        // W2 GEMM (+attn residual, fp32 out)
        gemm_bf16x3_kernel<<<gD, 256>>>(y1h, y1l,
            w2h + l * W2_SZ, w2l + l * W2_SZ,
            b2 + oD, attn, y2, nullptr, nullptr, M, DMODEL, FDIM);

        // LN2 (fp32 only)
        float* dst = (l == 0) ? xb : (float*)d_out;
        ln_kernel<<<M, 256>>>(y2, ln2_scale + oD, ln2_bias + oD,
                              dst, nullptr, nullptr);
        x = xb;
    }
}

// round 7
// speedup vs baseline: 1.1947x; 1.0040x over previous
#include <cuda_runtime.h>
#include <cuda_bf16.h>
#include <math.h>
#include <stdint.h>

// ---------------------------------------------------------------------------
// EmformerEncoder  B=2, T=1248, D=1024, H=16, DK=64, F=4096, L=2.
// Analytic block-sparse mask (CHUNK=128, LEFT=128, RIGHT=32).
// Round 7: tcgen05 unavailable (PTX target compute_103). HMMA bf16x3 GEMM
//          restructured: BK=32, 3-stage cp.async, ONE barrier/iter, 2 CTAs/SM.
// ---------------------------------------------------------------------------

#define TTOT   1248
#define NRIGHT 224
#define BATCH  2
#define MROWS  (BATCH * TTOT)   // 2496
#define DMODEL 1024
#define NHEAD  16
#define DK     64
#define FDIM   4096
#define QKVW   3072

// ---- scratch (device globals) ---------------------------------------------
__device__ float g_h[MROWS * DMODEL];     // LN_in fp32 (attn residual)
__device__ float g_attn[MROWS * DMODEL];
__device__ float g_y2[MROWS * DMODEL];
__device__ float g_x[MROWS * DMODEL];
__device__ float g_qkv[MROWS * QKVW];
__device__ __nv_bfloat16 g_ah[MROWS * DMODEL];  // LN split out
__device__ __nv_bfloat16 g_al[MROWS * DMODEL];
__device__ __nv_bfloat16 g_y1h[MROWS * FDIM];   // W1 GEMM split out
__device__ __nv_bfloat16 g_y1l[MROWS * FDIM];
__device__ unsigned g_wqkvh[2][(DMODEL/2) * QKVW];
__device__ unsigned g_wqkvl[2][(DMODEL/2) * QKVW];
__device__ unsigned g_w1h[2][(DMODEL/2) * FDIM];
__device__ unsigned g_w1l[2][(DMODEL/2) * FDIM];
__device__ unsigned g_w2h[2][(FDIM/2) * DMODEL];
__device__ unsigned g_w2l[2][(FDIM/2) * DMODEL];
__device__ float g_bqkv[2][QKVW];

// ---- helpers ---------------------------------------------------------------
__device__ __forceinline__ void split_bf16(float x, __nv_bfloat16& h, __nv_bfloat16& l)
{
    h = __float2bfloat16_rn(x);
    l = __float2bfloat16_rn(x - __bfloat162float(h));
}
__device__ __forceinline__ unsigned packb(__nv_bfloat16 a, __nv_bfloat16 b)
{
    __nv_bfloat162 p; p.x = a; p.y = b;
    return *(unsigned*)&p;
}
__device__ __forceinline__ void mma_bf16(float* c, const unsigned* a,
                                         unsigned b0, unsigned b1)
{
    asm volatile(
        "mma.sync.aligned.m16n8k16.row.col.f32.bf16.bf16.f32 "
        "{%0,%1,%2,%3}, {%4,%5,%6,%7}, {%8,%9}, {%0,%1,%2,%3};"
        : "+f"(c[0]), "+f"(c[1]), "+f"(c[2]), "+f"(c[3])
        : "r"(a[0]), "r"(a[1]), "r"(a[2]), "r"(a[3]), "r"(b0), "r"(b1));
}
__device__ __forceinline__ void cp16s(uint32_t dst, const void* src, bool pred)
{
    int sz = pred ? 16 : 0;
    asm volatile("cp.async.cg.shared.global [%0], [%1], 16, %2;\n"
                 :: "r"(dst), "l"(src), "r"(sz));
}
#define CP_COMMIT() asm volatile("cp.async.commit_group;\n")

// ---------------------------------------------------------------------------
// Weight packing: one launch per weight class, both layers via grid.z.
// Output: k-pair packed uint32 hi/lo [K/2][N].
// ---------------------------------------------------------------------------
__global__ void pack_qkv_kernel(const float* __restrict__ Wq,
                                const float* __restrict__ Wk,
                                const float* __restrict__ Wv,
                                unsigned* __restrict__ Dh,
                                unsigned* __restrict__ Dl)
{
    int n  = blockIdx.x * 256 + threadIdx.x;     // 0..3071
    int kp = blockIdx.y;                          // 0..511
    int l  = blockIdx.z;
    const float* W = (n < DMODEL) ? Wq : (n < 2 * DMODEL) ? Wk : Wv;
    int nc = n & (DMODEL - 1);
    W += (size_t)l * DMODEL * DMODEL;
    float e = W[(size_t)(2 * kp) * DMODEL + nc];
    float o = W[(size_t)(2 * kp + 1) * DMODEL + nc];
    __nv_bfloat16 eh, el, oh, ol;
    split_bf16(e, eh, el); split_bf16(o, oh, ol);
    size_t idx = (size_t)l * (DMODEL/2) * QKVW + (size_t)kp * QKVW + n;
    Dh[idx] = packb(eh, oh);
    Dl[idx] = packb(el, ol);
}

__global__ void pack_w_kernel(const float* __restrict__ W,
                              unsigned* __restrict__ Dh,
                              unsigned* __restrict__ Dl,
                              int N, int Khalf)
{
    int n  = blockIdx.x * 256 + threadIdx.x;
    int kp = blockIdx.y;
    int l  = blockIdx.z;
    W += (size_t)l * (2 * (size_t)Khalf) * N;
    float e = W[(size_t)(2 * kp) * N + n];
    float o = W[(size_t)(2 * kp + 1) * N + n];
    __nv_bfloat16 eh, el, oh, ol;
    split_bf16(e, eh, el); split_bf16(o, oh, ol);
    size_t idx = (size_t)l * Khalf * N + (size_t)kp * N + n;
    Dh[idx] = packb(eh, oh);
    Dl[idx] = packb(el, ol);
}

__global__ void concat3_kernel(const float* __restrict__ a,
                               const float* __restrict__ b,
                               const float* __restrict__ c,
                               float* __restrict__ d)
{
    int i = blockIdx.x * 256 + threadIdx.x;
    int l = blockIdx.y;
    const float* s = (i < DMODEL) ? a : (i < 2 * DMODEL) ? b : c;
    d[(size_t)l * QKVW + i] = s[(size_t)l * DMODEL + (i & (DMODEL - 1))];
}

// ---------------------------------------------------------------------------
// LayerNorm + optional fp32 out + optional bf16 hi/lo split out.
// ---------------------------------------------------------------------------
__global__ void ln_kernel(const float* __restrict__ X,
                          const float* __restrict__ sc,
                          const float* __restrict__ bi,
                          float* __restrict__ Yf,
                          __nv_bfloat16* __restrict__ Yh,
                          __nv_bfloat16* __restrict__ Yl)
{
    int row = blockIdx.x;
    int t   = threadIdx.x;
    const float4* xr = (const float4*)(X + (size_t)row * DMODEL);
    float4 v = xr[t];
    float s  = v.x + v.y + v.z + v.w;
    float ss = v.x*v.x + v.y*v.y + v.z*v.z + v.w*v.w;
    #pragma unroll
    for (int off = 16; off; off >>= 1) {
        s  += __shfl_xor_sync(0xffffffffu, s,  off);
        ss += __shfl_xor_sync(0xffffffffu, ss, off);
    }
    __shared__ float redS[8], redQ[8];
    int w = t >> 5;
    if ((t & 31) == 0) { redS[w] = s; redQ[w] = ss; }
    __syncthreads();
    float S = 0.f, Q = 0.f;
    #pragma unroll
    for (int i = 0; i < 8; i++) { S += redS[i]; Q += redQ[i]; }
    float mean = S * (1.0f / DMODEL);
    float var  = Q * (1.0f / DMODEL) - mean * mean;
    float r    = rsqrtf(var + 1e-5f);
    float4 scv = ((const float4*)sc)[t];
    float4 bv  = ((const float4*)bi)[t];
    float4 o;
    o.x = (v.x - mean) * r * scv.x + bv.x;
    o.y = (v.y - mean) * r * scv.y + bv.y;
    o.z = (v.z - mean) * r * scv.z + bv.z;
    o.w = (v.w - mean) * r * scv.w + bv.w;
    size_t base = (size_t)row * DMODEL;
    if (Yf) ((float4*)(Yf + base))[t] = o;
    if (Yh) {
        __nv_bfloat16 h0,l0,h1,l1,h2,l2,h3,l3;
        split_bf16(o.x, h0, l0); split_bf16(o.y, h1, l1);
        split_bf16(o.z, h2, l2); split_bf16(o.w, h3, l3);
        uint2 wh, wl;
        wh.x = packb(h0, h1); wh.y = packb(h2, h3);
        wl.x = packb(l0, l1); wl.y = packb(l2, l3);
        ((uint2*)(Yh + base))[t] = wh;
        ((uint2*)(Yl + base))[t] = wl;
    }
}

// ---------------------------------------------------------------------------
// bf16x3 HMMA GEMM, restructured.
// A: bf16 hi/lo row-major [M][K]. B: packed k-pair uint32 hi/lo [K/2][N].
// CTA tile 128x128, BK=32, 3-stage cp.async pipeline, ONE barrier per iter,
// 2 CTAs/SM. 8 warps (2x4), warp tile 64x32.
// Stage layout (words): Ah 128*20 | Al 128*20 | Bh 16*136 | Bl 16*136
//   = 9472 words = 37888 B/stage; 3 stages = 113664 B dynamic smem.
// A row stride 20 words (bank-conflict-free: (g*20+qd)%32 distinct);
// B row stride 136 words (proven conflict-free since round 2).
// ---------------------------------------------------------------------------
#define ST_WORDS   9472
#define ST_BYTES   37888
#define OFF_AL     2560          // words
#define OFF_BH     5120
#define OFF_BL     7296
#define GEMM_SMEM  (3 * ST_BYTES)

__global__ __launch_bounds__(256, 2)
void gemm_bf16x3_kernel(const __nv_bfloat16* __restrict__ Agh,
                        const __nv_bfloat16* __restrict__ Agl,
                        const unsigned* __restrict__ Bgh,
                        const unsigned* __restrict__ Bgl,
                        const float* __restrict__ bias,
                        const float* __restrict__ res,
                        float* __restrict__ C,
                        __nv_bfloat16* __restrict__ Ch,
                        __nv_bfloat16* __restrict__ Cl,
                        int M, int N, int K)
{
    extern __shared__ __align__(16) unsigned smw[];
    const uint32_t sb = (uint32_t)__cvta_generic_to_shared(smw);

    const int bm = blockIdx.y * 128;
    const int bn = blockIdx.x * 128;
    const int tid  = threadIdx.x;
    const int lane = tid & 31;
    const int wid  = tid >> 5;
    const int wm = (wid >> 2) * 64;
    const int wn = (wid & 3) * 32;
    const int g  = lane >> 2;
    const int qd = lane & 3;

    float acc[4][4][4];
    #pragma unroll
    for (int i = 0; i < 4; i++)
        #pragma unroll
        for (int j = 0; j < 4; j++)
            #pragma unroll
            for (int r = 0; r < 4; r++) acc[i][j][r] = 0.f;

    const int nIter = K >> 5;    // BK = 32

    // 2048 cp16 per stage -> 8 per thread
    #define LOAD_CHUNK(st, cc)                                                  \
    {                                                                           \
        uint32_t stb = sb + (st) * ST_BYTES;                                    \
        int kb = (cc) << 5;                                                     \
        _Pragma("unroll")                                                       \
        for (int j = 0; j < 8; j++) {                                           \
            int idx  = tid + j * 256;                                           \
            int part = idx >> 9;                                                \
            int sub  = idx & 511;                                               \
            if (part < 2) {                                                     \
                int row = sub >> 2, seg = sub & 3;                              \
                bool pr = (bm + row) < M;                                       \
                const __nv_bfloat16* gp = (part == 0 ? Agh : Agl)               \
                    + (size_t)(bm + row) * K + kb + seg * 8;                    \
                cp16s(stb + part * 10240 + row * 80 + seg * 16, gp, pr);        \
            } else {                                                            \
                int kp = sub >> 5, seg = sub & 31;                              \
                const unsigned* gp = (part == 2 ? Bgh : Bgl)                    \
                    + (size_t)((kb >> 1) + kp) * N + bn + seg * 4;              \
                cp16s(stb + 20480 + (part - 2) * 8704 + kp * 544 + seg * 16,    \
                      gp, true);                                                \
            }                                                                   \
        }                                                                       \
    }

    LOAD_CHUNK(0, 0); CP_COMMIT();
    LOAD_CHUNK(1, 1); CP_COMMIT();

    for (int i = 0; i < nIter; i++) {
        asm volatile("cp.async.wait_group 1;\n");
        __syncthreads();
        int nx = i + 2;
        if (nx < nIter) {
            int stn = nx - (nx / 3) * 3;
            LOAD_CHUNK(stn, nx);
        }
        CP_COMMIT();

        const int s = i - (i / 3) * 3;
        const unsigned* Ahw = smw + s * ST_WORDS;
        const unsigned* Alw = Ahw + OFF_AL;
        const unsigned* Bhw = Ahw + OFF_BH;
        const unsigned* Blw = Ahw + OFF_BL;

        #pragma unroll
        for (int k16 = 0; k16 < 2; k16++) {
            unsigned ah[4][4], al[4][4];
            #pragma unroll
            for (int mi = 0; mi < 4; mi++) {
                int ra = (wm + mi * 16 + g) * 20 + k16 * 8 + qd;
                int rb = ra + 160;
                ah[mi][0] = Ahw[ra];     ah[mi][1] = Ahw[rb];
                ah[mi][2] = Ahw[ra + 4]; ah[mi][3] = Ahw[rb + 4];
                al[mi][0] = Alw[ra];     al[mi][1] = Alw[rb];
                al[mi][2] = Alw[ra + 4]; al[mi][3] = Alw[rb + 4];
            }
            #pragma unroll
            for (int ni = 0; ni < 4; ni++) {
                int n0 = wn + ni * 8 + g;
                unsigned bh0 = Bhw[(k16 * 8 + qd) * 136 + n0];
                unsigned bh1 = Bhw[(k16 * 8 + 4 + qd) * 136 + n0];
                unsigned bl0 = Blw[(k16 * 8 + qd) * 136 + n0];
                unsigned bl1 = Blw[(k16 * 8 + 4 + qd) * 136 + n0];
                #pragma unroll
                for (int mi = 0; mi < 4; mi++) {
                    mma_bf16(acc[mi][ni], ah[mi], bh0, bh1);
                    mma_bf16(acc[mi][ni], ah[mi], bl0, bl1);
                    mma_bf16(acc[mi][ni], al[mi], bh0, bh1);
                }
            }
        }
    }
    #undef LOAD_CHUNK

    // epilogue
    #pragma unroll
    for (int mi = 0; mi < 4; mi++) {
        #pragma unroll
        for (int ni = 0; ni < 4; ni++) {
            #pragma unroll
            for (int half = 0; half < 2; half++) {
                int row = bm + wm + mi * 16 + g + half * 8;
                if (row >= M) continue;
                int cc = bn + wn + ni * 8 + qd * 2;
                float2 bb = *(const float2*)&bias[cc];
                float ox = acc[mi][ni][2 * half + 0] + bb.x;
                float oy = acc[mi][ni][2 * half + 1] + bb.y;
                if (Ch) {
                    __nv_bfloat16 hx, lx, hy, ly;
                    split_bf16(ox, hx, lx);
                    split_bf16(oy, hy, ly);
                    size_t wi = ((size_t)row * N + cc) >> 1;
                    ((unsigned*)Ch)[wi] = packb(hx, hy);
                    ((unsigned*)Cl)[wi] = packb(lx, ly);
                } else {
                    if (res) {
                        float2 rr = *(const float2*)&res[(size_t)row * N + cc];
                        ox += rr.x; oy += rr.y;
                    }
                    float2 o; o.x = ox; o.y = oy;
                    *(float2*)&C[(size_t)row * N + cc] = o;
                }
            }
        }
    }
}

// ---------------------------------------------------------------------------
// Attention: warp-per-query, key-parallel lanes. 512 threads (16 warps).
// ---------------------------------------------------------------------------
__global__ __launch_bounds__(512, 1)
void attn_kernel(const float* __restrict__ qkv,
                 const float* __restrict__ Hh,
                 float* __restrict__ O)
{
    int ci = blockIdx.x;
    int hh = blockIdx.y;
    int b  = blockIdx.z;

    extern __shared__ float sm[];
    float2* Kt2 = (float2*)sm;          // [32 d-pairs][288 keys]
    float*  Vs  = sm + 18432;           // [288 keys][64]

    int nkr   = (ci < 7) ? 32 : 0;
    int body0 = (ci >= 1) ? 128 * (ci - 1) : 0;
    int nk    = nkr + (128 * (ci + 1) - body0);
    int nq    = (ci < 7) ? 160 : 128;
    int base  = b * TTOT;
    int tid   = threadIdx.x;

    if (tid < nk) {
        int key  = tid;
        int krow = (key < nkr) ? (32 * ci + key) : (NRIGHT + body0 + (key - nkr));
        const float4* kp4 = (const float4*)&qkv[(size_t)(base + krow) * QKVW + DMODEL + hh * DK];
        #pragma unroll
        for (int d4 = 0; d4 < 16; d4++) {
            float4 v = kp4[d4];
            Kt2[(2 * d4) * 288 + key]     = make_float2(v.x, v.y);
            Kt2[(2 * d4 + 1) * 288 + key] = make_float2(v.z, v.w);
        }
    }
    for (int idx = tid; idx < nk * 16; idx += 512) {
        int key = idx >> 4;
        int d4  = idx & 15;
        int krow = (key < nkr) ? (32 * ci + key) : (NRIGHT + body0 + (key - nkr));
        float4 v = *(const float4*)&qkv[(size_t)(base + krow) * QKVW + 2 * DMODEL + hh * DK + d4 * 4];
        *(float4*)&Vs[key * 64 + d4 * 4] = v;
    }
    __syncthreads();

    int warp = tid >> 5;
    int lane = tid & 31;

    for (int qi = warp; qi < nq; qi += 16) {
        int qrow;
        if (ci < 7) qrow = (qi < 32) ? (32 * ci + qi) : (NRIGHT + 128 * ci + qi - 32);
        else        qrow = NRIGHT + 128 * 7 + qi;

        const float4* qp = (const float4*)&qkv[(size_t)(base + qrow) * QKVW + hh * DK];
        float q[64];
        #pragma unroll
        for (int d4 = 0; d4 < 16; d4++) {
            float4 t = qp[d4];
            q[4*d4+0] = t.x * 0.125f;
            q[4*d4+1] = t.y * 0.125f;
            q[4*d4+2] = t.z * 0.125f;
            q[4*d4+3] = t.w * 0.125f;
        }

        float m = -1e30f, l = 0.f, o0 = 0.f, o1 = 0.f;

        for (int j0 = 0; j0 < nk; j0 += 32) {
            int key = j0 + lane;
            float s = 0.f;
            #pragma unroll
            for (int d2 = 0; d2 < 32; d2++) {
                float2 kk = Kt2[d2 * 288 + key];
                s += q[2*d2] * kk.x + q[2*d2+1] * kk.y;
            }
            float mb = s;
            #pragma unroll
            for (int off = 16; off; off >>= 1)
                mb = fmaxf(mb, __shfl_xor_sync(0xffffffffu, mb, off));
            float mnew = fmaxf(m, mb);
            float c = __expf(m - mnew);
            float p = __expf(s - mnew);
            float ps = p;
            #pragma unroll
            for (int off = 16; off; off >>= 1)
                ps += __shfl_xor_sync(0xffffffffu, ps, off);
            l = l * c + ps;
            o0 *= c; o1 *= c;
            m = mnew;
            const float2* vb = (const float2*)&Vs[j0 * 64];
            #pragma unroll
            for (int jj = 0; jj < 32; jj++) {
                float pj = __shfl_sync(0xffffffffu, p, jj);
                float2 vv = vb[jj * 32 + lane];
                o0 += pj * vv.x;
                o1 += pj * vv.y;
            }
        }

        float inv = 1.0f / l;
        size_t ooff = (size_t)(base + qrow) * DMODEL + hh * DK + 2 * lane;
        float2 hv = *(const float2*)&Hh[ooff];
        float2 out;
        out.x = o0 * inv + hv.x;
        out.y = o1 * inv + hv.y;
        *(float2*)&O[ooff] = out;
    }
}

// ---------------------------------------------------------------------------
extern "C" void kernel_launch(void* const* d_in, const int* in_sizes, int n_in,
                              void* d_out, int out_size)
{
    const float* input       = (const float*)d_in[0];
    const float* ln_in_scale = (const float*)d_in[1];
    const float* ln_in_bias  = (const float*)d_in[2];
    const float* Wq          = (const float*)d_in[3];
    const float* bq          = (const float*)d_in[4];
    const float* Wk          = (const float*)d_in[5];
    const float* bk          = (const float*)d_in[6];
    const float* Wv          = (const float*)d_in[7];
    const float* bv          = (const float*)d_in[8];
    const float* ln1_scale   = (const float*)d_in[9];
    const float* ln1_bias    = (const float*)d_in[10];
    const float* W1          = (const float*)d_in[11];
    const float* b1          = (const float*)d_in[12];
    const float* W2          = (const float*)d_in[13];
    const float* b2          = (const float*)d_in[14];
    const float* ln2_scale   = (const float*)d_in[15];
    const float* ln2_bias    = (const float*)d_in[16];
    // d_in[17] = mask: unused (analytic)

    float *h, *attn, *y2, *xb, *qkv, *bqkv;
    __nv_bfloat16 *ah, *al, *y1h, *y1l;
    unsigned *wqkvh, *wqkvl, *w1h, *w1l, *w2h, *w2l;
    cudaGetSymbolAddress((void**)&h,     g_h);
    cudaGetSymbolAddress((void**)&attn,  g_attn);
    cudaGetSymbolAddress((void**)&y2,    g_y2);
    cudaGetSymbolAddress((void**)&xb,    g_x);
    cudaGetSymbolAddress((void**)&qkv,   g_qkv);
    cudaGetSymbolAddress((void**)&ah,    g_ah);
    cudaGetSymbolAddress((void**)&al,    g_al);
    cudaGetSymbolAddress((void**)&y1h,   g_y1h);
    cudaGetSymbolAddress((void**)&y1l,   g_y1l);
    cudaGetSymbolAddress((void**)&wqkvh, g_wqkvh);
    cudaGetSymbolAddress((void**)&wqkvl, g_wqkvl);
    cudaGetSymbolAddress((void**)&w1h,   g_w1h);
    cudaGetSymbolAddress((void**)&w1l,   g_w1l);
    cudaGetSymbolAddress((void**)&w2h,   g_w2h);
    cudaGetSymbolAddress((void**)&w2l,   g_w2l);
    cudaGetSymbolAddress((void**)&bqkv,  g_bqkv);

    cudaFuncSetAttribute(attn_kernel,
                         cudaFuncAttributeMaxDynamicSharedMemorySize, 147456);
    cudaFuncSetAttribute(gemm_bf16x3_kernel,
                         cudaFuncAttributeMaxDynamicSharedMemorySize, GEMM_SMEM);

    const int M = MROWS;
    const size_t WQKV_SZ = (size_t)(DMODEL/2) * QKVW;
    const size_t W1_SZ   = (size_t)(DMODEL/2) * FDIM;
    const size_t W2_SZ   = (size_t)(FDIM/2) * DMODEL;

    // ---- weight packing: 3 launches + bias concat (both layers each) -------
    {
        dim3 gq(QKVW / 256, DMODEL / 2, 2);
        pack_qkv_kernel<<<gq, 256>>>(Wq, Wk, Wv, wqkvh, wqkvl);
        dim3 g1(FDIM / 256, DMODEL / 2, 2);
        pack_w_kernel<<<g1, 256>>>(W1, w1h, w1l, FDIM, DMODEL / 2);
        dim3 g2(DMODEL / 256, FDIM / 2, 2);
        pack_w_kernel<<<g2, 256>>>(W2, w2h, w2l, DMODEL, FDIM / 2);
        dim3 gc(QKVW / 256, 2);
        concat3_kernel<<<gc, 256>>>(bq, bk, bv, bqkv);
    }

    dim3 gQKV(QKVW / 128,   (M + 127) / 128);   // (24, 20)
    dim3 gF  (FDIM / 128,   (M + 127) / 128);   // (32, 20)
    dim3 gD  (DMODEL / 128, (M + 127) / 128);   // (8, 20)
    dim3 attnGrid(8, NHEAD, BATCH);

    const float* x = input;
    for (int l = 0; l < 2; l++) {
        size_t oD = (size_t)l * DMODEL;
        size_t oF = (size_t)l * FDIM;

        // LN_in: fp32 h (attn residual) + bf16 split for QKV GEMM
        ln_kernel<<<M, 256>>>(x, ln_in_scale + oD, ln_in_bias + oD, h, ah, al);

        // fused QKV GEMM (fp32 out)
        gemm_bf16x3_kernel<<<gQKV, 256, GEMM_SMEM>>>(ah, al,
            wqkvh + l * WQKV_SZ, wqkvl + l * WQKV_SZ,
            bqkv + l * QKVW, nullptr, qkv, nullptr, nullptr, M, QKVW, DMODEL);

        // attention (+h residual)
        attn_kernel<<<attnGrid, 512, 147456>>>(qkv, h, attn);

        // LN1: bf16 split only
        ln_kernel<<<M, 256>>>(attn, ln1_scale + oD, ln1_bias + oD,
                              nullptr, ah, al);

        // W1 GEMM -> bf16 hi/lo y1 (separate buffers; no aliasing)
        gemm_bf16x3_kernel<<<gF, 256, GEMM_SMEM>>>(ah, al,
            w1h + l * W1_SZ, w1l + l * W1_SZ,
            b1 + oF, nullptr, nullptr, y1h, y1l, M, FDIM, DMODEL);

        // W2 GEMM (+attn residual, fp32 out)
        gemm_bf16x3_kernel<<<gD, 256, GEMM_SMEM>>>(y1h, y1l,
            w2h + l * W2_SZ, w2l + l * W2_SZ,
            b2 + oD, attn, y2, nullptr, nullptr, M, DMODEL, FDIM);

        // LN2 (fp32 only)
        float* dst = (l == 0) ? xb : (float*)d_out;
        ln_kernel<<<M, 256>>>(y2, ln2_scale + oD, ln2_bias + oD,
                              dst, nullptr, nullptr);
        x = xb;
    }
}

// round 8
// speedup vs baseline: 1.5870x; 1.3283x over previous
#include <cuda_runtime.h>
#include <cuda_bf16.h>
#include <cuda_fp16.h>
#include <math.h>
#include <stdint.h>

// ---------------------------------------------------------------------------
// EmformerEncoder  B=2, T=1248, D=1024, H=16, DK=64, F=4096, L=2.
// Analytic block-sparse mask (CHUNK=128, LEFT=128, RIGHT=32).
// Round 8: HMMA pipe is the wall (legacy mma.sync ~180 TF/s ceiling; tcgen05
//          not available under compute_103). Cut MMA count 33%: fp16 2-term
//          scheme — A = fp16(x) single, W = 64*(wh+wl) fp16 split (exact),
//          epilogue scales by 1/64. Predicted rel_err ~4e-4.
// ---------------------------------------------------------------------------

#define TTOT   1248
#define NRIGHT 224
#define BATCH  2
#define MROWS  (BATCH * TTOT)   // 2496
#define DMODEL 1024
#define NHEAD  16
#define DK     64
#define FDIM   4096
#define QKVW   3072

// ---- scratch (device globals) ---------------------------------------------
__device__ float g_h[MROWS * DMODEL];     // LN_in fp32 (attn residual)
__device__ float g_attn[MROWS * DMODEL];
__device__ float g_y2[MROWS * DMODEL];
__device__ float g_x[MROWS * DMODEL];
__device__ float g_qkv[MROWS * QKVW];
__device__ __half g_ax[MROWS * DMODEL];   // LN fp16 activation
__device__ __half g_y1[MROWS * FDIM];     // W1 GEMM fp16 out
__device__ unsigned g_wqkvh[2][(DMODEL/2) * QKVW];
__device__ unsigned g_wqkvl[2][(DMODEL/2) * QKVW];
__device__ unsigned g_w1h[2][(DMODEL/2) * FDIM];
__device__ unsigned g_w1l[2][(DMODEL/2) * FDIM];
__device__ unsigned g_w2h[2][(FDIM/2) * DMODEL];
__device__ unsigned g_w2l[2][(FDIM/2) * DMODEL];
__device__ float g_bqkv[2][QKVW];

#define WSCALE     64.0f
#define INV_WSCALE 0.015625f

// ---- helpers ---------------------------------------------------------------
__device__ __forceinline__ void split_h(float x, __half& h, __half& l)
{
    h = __float2half_rn(x);
    l = __float2half_rn(x - __half2float(h));
}
__device__ __forceinline__ unsigned packh(__half a, __half b)
{
    __half2 p; p.x = a; p.y = b;
    return *(unsigned*)&p;
}
__device__ __forceinline__ void mma_f16(float* c, const unsigned* a,
                                        unsigned b0, unsigned b1)
{
    asm volatile(
        "mma.sync.aligned.m16n8k16.row.col.f32.f16.f16.f32 "
        "{%0,%1,%2,%3}, {%4,%5,%6,%7}, {%8,%9}, {%0,%1,%2,%3};"
        : "+f"(c[0]), "+f"(c[1]), "+f"(c[2]), "+f"(c[3])
        : "r"(a[0]), "r"(a[1]), "r"(a[2]), "r"(a[3]), "r"(b0), "r"(b1));
}
__device__ __forceinline__ void cp16s(uint32_t dst, const void* src, bool pred)
{
    int sz = pred ? 16 : 0;
    asm volatile("cp.async.cg.shared.global [%0], [%1], 16, %2;\n"
                 :: "r"(dst), "l"(src), "r"(sz));
}
#define CP_COMMIT() asm volatile("cp.async.commit_group;\n")

// ---------------------------------------------------------------------------
// Weight packing (x64 scale, fp16 hi/lo, k-pair packed [K/2][N]).
// ---------------------------------------------------------------------------
__global__ void pack_qkv_kernel(const float* __restrict__ Wq,
                                const float* __restrict__ Wk,
                                const float* __restrict__ Wv,
                                unsigned* __restrict__ Dh,
                                unsigned* __restrict__ Dl)
{
    int n  = blockIdx.x * 256 + threadIdx.x;     // 0..3071
    int kp = blockIdx.y;                          // 0..511
    int l  = blockIdx.z;
    const float* W = (n < DMODEL) ? Wq : (n < 2 * DMODEL) ? Wk : Wv;
    int nc = n & (DMODEL - 1);
    W += (size_t)l * DMODEL * DMODEL;
    float e = W[(size_t)(2 * kp) * DMODEL + nc] * WSCALE;
    float o = W[(size_t)(2 * kp + 1) * DMODEL + nc] * WSCALE;
    __half eh, el, oh, ol;
    split_h(e, eh, el); split_h(o, oh, ol);
    size_t idx = (size_t)l * (DMODEL/2) * QKVW + (size_t)kp * QKVW + n;
    Dh[idx] = packh(eh, oh);
    Dl[idx] = packh(el, ol);
}

__global__ void pack_w_kernel(const float* __restrict__ W,
                              unsigned* __restrict__ Dh,
                              unsigned* __restrict__ Dl,
                              int N, int Khalf)
{
    int n  = blockIdx.x * 256 + threadIdx.x;
    int kp = blockIdx.y;
    int l  = blockIdx.z;
    W += (size_t)l * (2 * (size_t)Khalf) * N;
    float e = W[(size_t)(2 * kp) * N + n] * WSCALE;
    float o = W[(size_t)(2 * kp + 1) * N + n] * WSCALE;
    __half eh, el, oh, ol;
    split_h(e, eh, el); split_h(o, oh, ol);
    size_t idx = (size_t)l * Khalf * N + (size_t)kp * N + n;
    Dh[idx] = packh(eh, oh);
    Dl[idx] = packh(el, ol);
}

__global__ void concat3_kernel(const float* __restrict__ a,
                               const float* __restrict__ b,
                               const float* __restrict__ c,
                               float* __restrict__ d)
{
    int i = blockIdx.x * 256 + threadIdx.x;
    int l = blockIdx.y;
    const float* s = (i < DMODEL) ? a : (i < 2 * DMODEL) ? b : c;
    d[(size_t)l * QKVW + i] = s[(size_t)l * DMODEL + (i & (DMODEL - 1))];
}

// ---------------------------------------------------------------------------
// LayerNorm + optional fp32 out + optional fp16 out.
// ---------------------------------------------------------------------------
__global__ void ln_kernel(const float* __restrict__ X,
                          const float* __restrict__ sc,
                          const float* __restrict__ bi,
                          float* __restrict__ Yf,
                          __half* __restrict__ Yh)
{
    int row = blockIdx.x;
    int t   = threadIdx.x;
    const float4* xr = (const float4*)(X + (size_t)row * DMODEL);
    float4 v = xr[t];
    float s  = v.x + v.y + v.z + v.w;
    float ss = v.x*v.x + v.y*v.y + v.z*v.z + v.w*v.w;
    #pragma unroll
    for (int off = 16; off; off >>= 1) {
        s  += __shfl_xor_sync(0xffffffffu, s,  off);
        ss += __shfl_xor_sync(0xffffffffu, ss, off);
    }
    __shared__ float redS[8], redQ[8];
    int w = t >> 5;
    if ((t & 31) == 0) { redS[w] = s; redQ[w] = ss; }
    __syncthreads();
    float S = 0.f, Q = 0.f;
    #pragma unroll
    for (int i = 0; i < 8; i++) { S += redS[i]; Q += redQ[i]; }
    float mean = S * (1.0f / DMODEL);
    float var  = Q * (1.0f / DMODEL) - mean * mean;
    float r    = rsqrtf(var + 1e-5f);
    float4 scv = ((const float4*)sc)[t];
    float4 bv  = ((const float4*)bi)[t];
    float4 o;
    o.x = (v.x - mean) * r * scv.x + bv.x;
    o.y = (v.y - mean) * r * scv.y + bv.y;
    o.z = (v.z - mean) * r * scv.z + bv.z;
    o.w = (v.w - mean) * r * scv.w + bv.w;
    size_t base = (size_t)row * DMODEL;
    if (Yf) ((float4*)(Yf + base))[t] = o;
    if (Yh) {
        uint2 wh;
        wh.x = packh(__float2half_rn(o.x), __float2half_rn(o.y));
        wh.y = packh(__float2half_rn(o.z), __float2half_rn(o.w));
        ((uint2*)(Yh + base))[t] = wh;
    }
}

// ---------------------------------------------------------------------------
// fp16x2 HMMA GEMM.
// A: fp16 row-major [M][K]. B: packed k-pair uint32 hi/lo [K/2][N] (x64).
// CTA tile 128x128, BK=32, 3-stage cp.async, one barrier/iter, 2 CTAs/SM.
// Stage (words): A 128*20 | Bh 16*136 | Bl 16*136 = 6912 w = 27648 B.
// Epilogue: C = acc/64 + bias (+res)  OR fp16 out (y1).
// ---------------------------------------------------------------------------
#define ST_WORDS   6912
#define ST_BYTES   27648
#define OFF_BH     2560          // words
#define OFF_BL     4736
#define GEMM_SMEM  (3 * ST_BYTES)

__global__ __launch_bounds__(256, 2)
void gemm_fp16x2_kernel(const __half* __restrict__ Ag,
                        const unsigned* __restrict__ Bgh,
                        const unsigned* __restrict__ Bgl,
                        const float* __restrict__ bias,
                        const float* __restrict__ res,
                        float* __restrict__ C,
                        __half* __restrict__ Ch,
                        int M, int N, int K)
{
    extern __shared__ __align__(16) unsigned smw[];
    const uint32_t sb = (uint32_t)__cvta_generic_to_shared(smw);

    const int bm = blockIdx.y * 128;
    const int bn = blockIdx.x * 128;
    const int tid  = threadIdx.x;
    const int lane = tid & 31;
    const int wid  = tid >> 5;
    const int wm = (wid >> 2) * 64;
    const int wn = (wid & 3) * 32;
    const int g  = lane >> 2;
    const int qd = lane & 3;

    float acc[4][4][4];
    #pragma unroll
    for (int i = 0; i < 4; i++)
        #pragma unroll
        for (int j = 0; j < 4; j++)
            #pragma unroll
            for (int r = 0; r < 4; r++) acc[i][j][r] = 0.f;

    const int nIter = K >> 5;    // BK = 32

    // 1536 cp16 per stage -> 6 per thread
    #define LOAD_CHUNK(st, cc)                                                  \
    {                                                                           \
        uint32_t stb = sb + (st) * ST_BYTES;                                    \
        int kb = (cc) << 5;                                                     \
        _Pragma("unroll")                                                       \
        for (int j = 0; j < 6; j++) {                                           \
            int idx  = tid + j * 256;                                           \
            int part = idx >> 9;                                                \
            int sub  = idx & 511;                                               \
            if (part == 0) {                                                    \
                int row = sub >> 2, seg = sub & 3;                              \
                bool pr = (bm + row) < M;                                       \
                const __half* gp = Ag + (size_t)(bm + row) * K + kb + seg * 8;  \
                cp16s(stb + row * 80 + seg * 16, gp, pr);                       \
            } else {                                                            \
                int kp = sub >> 5, seg = sub & 31;                              \
                const unsigned* gp = (part == 1 ? Bgh : Bgl)                    \
                    + (size_t)((kb >> 1) + kp) * N + bn + seg * 4;              \
                cp16s(stb + 10240 + (part - 1) * 8704 + kp * 544 + seg * 16,    \
                      gp, true);                                                \
            }                                                                   \
        }                                                                       \
    }

    LOAD_CHUNK(0, 0); CP_COMMIT();
    LOAD_CHUNK(1, 1); CP_COMMIT();

    for (int i = 0; i < nIter; i++) {
        asm volatile("cp.async.wait_group 1;\n");
        __syncthreads();
        int nx = i + 2;
        if (nx < nIter) {
            int stn = nx - (nx / 3) * 3;
            LOAD_CHUNK(stn, nx);
        }
        CP_COMMIT();

        const int s = i - (i / 3) * 3;
        const unsigned* Aw  = smw + s * ST_WORDS;
        const unsigned* Bhw = Aw + OFF_BH;
        const unsigned* Blw = Aw + OFF_BL;

        #pragma unroll
        for (int k16 = 0; k16 < 2; k16++) {
            unsigned af[4][4];
            #pragma unroll
            for (int mi = 0; mi < 4; mi++) {
                int ra = (wm + mi * 16 + g) * 20 + k16 * 8 + qd;
                int rb = ra + 160;
                af[mi][0] = Aw[ra];     af[mi][1] = Aw[rb];
                af[mi][2] = Aw[ra + 4]; af[mi][3] = Aw[rb + 4];
            }
            #pragma unroll
            for (int ni = 0; ni < 4; ni++) {
                int n0 = wn + ni * 8 + g;
                unsigned bh0 = Bhw[(k16 * 8 + qd) * 136 + n0];
                unsigned bh1 = Bhw[(k16 * 8 + 4 + qd) * 136 + n0];
                unsigned bl0 = Blw[(k16 * 8 + qd) * 136 + n0];
                unsigned bl1 = Blw[(k16 * 8 + 4 + qd) * 136 + n0];
                #pragma unroll
                for (int mi = 0; mi < 4; mi++) {
                    mma_f16(acc[mi][ni], af[mi], bh0, bh1);
                    mma_f16(acc[mi][ni], af[mi], bl0, bl1);
                }
            }
        }
    }
    #undef LOAD_CHUNK

    // epilogue: scale by 1/64, bias, +res or fp16 out
    #pragma unroll
    for (int mi = 0; mi < 4; mi++) {
        #pragma unroll
        for (int ni = 0; ni < 4; ni++) {
            #pragma unroll
            for (int half_ = 0; half_ < 2; half_++) {
                int row = bm + wm + mi * 16 + g + half_ * 8;
                if (row >= M) continue;
                int cc = bn + wn + ni * 8 + qd * 2;
                float2 bb = *(const float2*)&bias[cc];
                float ox = acc[mi][ni][2 * half_ + 0] * INV_WSCALE + bb.x;
                float oy = acc[mi][ni][2 * half_ + 1] * INV_WSCALE + bb.y;
                if (Ch) {
                    size_t wi = ((size_t)row * N + cc) >> 1;
                    ((unsigned*)Ch)[wi] =
                        packh(__float2half_rn(ox), __float2half_rn(oy));
                } else {
                    if (res) {
                        float2 rr = *(const float2*)&res[(size_t)row * N + cc];
                        ox += rr.x; oy += rr.y;
                    }
                    float2 o; o.x = ox; o.y = oy;
                    *(float2*)&C[(size_t)row * N + cc] = o;
                }
            }
        }
    }
}

// ---------------------------------------------------------------------------
// Attention: warp-per-query, key-parallel lanes. 512 threads (16 warps).
// ---------------------------------------------------------------------------
__global__ __launch_bounds__(512, 1)
void attn_kernel(const float* __restrict__ qkv,
                 const float* __restrict__ Hh,
                 float* __restrict__ O)
{
    int ci = blockIdx.x;
    int hh = blockIdx.y;
    int b  = blockIdx.z;

    extern __shared__ float sm[];
    float2* Kt2 = (float2*)sm;          // [32 d-pairs][288 keys]
    float*  Vs  = sm + 18432;           // [288 keys][64]

    int nkr   = (ci < 7) ? 32 : 0;
    int body0 = (ci >= 1) ? 128 * (ci - 1) : 0;
    int nk    = nkr + (128 * (ci + 1) - body0);
    int nq    = (ci < 7) ? 160 : 128;
    int base  = b * TTOT;
    int tid   = threadIdx.x;

    if (tid < nk) {
        int key  = tid;
        int krow = (key < nkr) ? (32 * ci + key) : (NRIGHT + body0 + (key - nkr));
        const float4* kp4 = (const float4*)&qkv[(size_t)(base + krow) * QKVW + DMODEL + hh * DK];
        #pragma unroll
        for (int d4 = 0; d4 < 16; d4++) {
            float4 v = kp4[d4];
            Kt2[(2 * d4) * 288 + key]     = make_float2(v.x, v.y);
            Kt2[(2 * d4 + 1) * 288 + key] = make_float2(v.z, v.w);
        }
    }
    for (int idx = tid; idx < nk * 16; idx += 512) {
        int key = idx >> 4;
        int d4  = idx & 15;
        int krow = (key < nkr) ? (32 * ci + key) : (NRIGHT + body0 + (key - nkr));
        float4 v = *(const float4*)&qkv[(size_t)(base + krow) * QKVW + 2 * DMODEL + hh * DK + d4 * 4];
        *(float4*)&Vs[key * 64 + d4 * 4] = v;
    }
    __syncthreads();

    int warp = tid >> 5;
    int lane = tid & 31;

    for (int qi = warp; qi < nq; qi += 16) {
        int qrow;
        if (ci < 7) qrow = (qi < 32) ? (32 * ci + qi) : (NRIGHT + 128 * ci + qi - 32);
        else        qrow = NRIGHT + 128 * 7 + qi;

        const float4* qp = (const float4*)&qkv[(size_t)(base + qrow) * QKVW + hh * DK];
        float q[64];
        #pragma unroll
        for (int d4 = 0; d4 < 16; d4++) {
            float4 t = qp[d4];
            q[4*d4+0] = t.x * 0.125f;
            q[4*d4+1] = t.y * 0.125f;
            q[4*d4+2] = t.z * 0.125f;
            q[4*d4+3] = t.w * 0.125f;
        }

        float m = -1e30f, l = 0.f, o0 = 0.f, o1 = 0.f;

        for (int j0 = 0; j0 < nk; j0 += 32) {
            int key = j0 + lane;
            float s = 0.f;
            #pragma unroll
            for (int d2 = 0; d2 < 32; d2++) {
                float2 kk = Kt2[d2 * 288 + key];
                s += q[2*d2] * kk.x + q[2*d2+1] * kk.y;
            }
            float mb = s;
            #pragma unroll
            for (int off = 16; off; off >>= 1)
                mb = fmaxf(mb, __shfl_xor_sync(0xffffffffu, mb, off));
            float mnew = fmaxf(m, mb);
            float c = __expf(m - mnew);
            float p = __expf(s - mnew);
            float ps = p;
            #pragma unroll
            for (int off = 16; off; off >>= 1)
                ps += __shfl_xor_sync(0xffffffffu, ps, off);
            l = l * c + ps;
            o0 *= c; o1 *= c;
            m = mnew;
            const float2* vb = (const float2*)&Vs[j0 * 64];
            #pragma unroll
            for (int jj = 0; jj < 32; jj++) {
                float pj = __shfl_sync(0xffffffffu, p, jj);
                float2 vv = vb[jj * 32 + lane];
                o0 += pj * vv.x;
                o1 += pj * vv.y;
            }
        }

        float inv = 1.0f / l;
        size_t ooff = (size_t)(base + qrow) * DMODEL + hh * DK + 2 * lane;
        float2 hv = *(const float2*)&Hh[ooff];
        float2 out;
        out.x = o0 * inv + hv.x;
        out.y = o1 * inv + hv.y;
        *(float2*)&O[ooff] = out;
    }
}

// ---------------------------------------------------------------------------
extern "C" void kernel_launch(void* const* d_in, const int* in_sizes, int n_in,
                              void* d_out, int out_size)
{
    const float* input       = (const float*)d_in[0];
    const float* ln_in_scale = (const float*)d_in[1];
    const float* ln_in_bias  = (const float*)d_in[2];
    const float* Wq          = (const float*)d_in[3];
    const float* bq          = (const float*)d_in[4];
    const float* Wk          = (const float*)d_in[5];
    const float* bk          = (const float*)d_in[6];
    const float* Wv          = (const float*)d_in[7];
    const float* bv          = (const float*)d_in[8];
    const float* ln1_scale   = (const float*)d_in[9];
    const float* ln1_bias    = (const float*)d_in[10];
    const float* W1          = (const float*)d_in[11];
    const float* b1          = (const float*)d_in[12];
    const float* W2          = (const float*)d_in[13];
    const float* b2          = (const float*)d_in[14];
    const float* ln2_scale   = (const float*)d_in[15];
    const float* ln2_bias    = (const float*)d_in[16];
    // d_in[17] = mask: unused (analytic)

    float *h, *attn, *y2, *xb, *qkv, *bqkv;
    __half *ax, *y1;
    unsigned *wqkvh, *wqkvl, *w1h, *w1l, *w2h, *w2l;
    cudaGetSymbolAddress((void**)&h,     g_h);
    cudaGetSymbolAddress((void**)&attn,  g_attn);
    cudaGetSymbolAddress((void**)&y2,    g_y2);
    cudaGetSymbolAddress((void**)&xb,    g_x);
    cudaGetSymbolAddress((void**)&qkv,   g_qkv);
    cudaGetSymbolAddress((void**)&ax,    g_ax);
    cudaGetSymbolAddress((void**)&y1,    g_y1);
    cudaGetSymbolAddress((void**)&wqkvh, g_wqkvh);
    cudaGetSymbolAddress((void**)&wqkvl, g_wqkvl);
    cudaGetSymbolAddress((void**)&w1h,   g_w1h);
    cudaGetSymbolAddress((void**)&w1l,   g_w1l);
    cudaGetSymbolAddress((void**)&w2h,   g_w2h);
    cudaGetSymbolAddress((void**)&w2l,   g_w2l);
    cudaGetSymbolAddress((void**)&bqkv,  g_bqkv);

    cudaFuncSetAttribute(attn_kernel,
                         cudaFuncAttributeMaxDynamicSharedMemorySize, 147456);
    cudaFuncSetAttribute(gemm_fp16x2_kernel,
                         cudaFuncAttributeMaxDynamicSharedMemorySize, GEMM_SMEM);

    const int M = MROWS;
    const size_t WQKV_SZ = (size_t)(DMODEL/2) * QKVW;
    const size_t W1_SZ   = (size_t)(DMODEL/2) * FDIM;
    const size_t W2_SZ   = (size_t)(FDIM/2) * DMODEL;

    // ---- weight packing: 3 launches + bias concat (both layers each) -------
    {
        dim3 gq(QKVW / 256, DMODEL / 2, 2);
        pack_qkv_kernel<<<gq, 256>>>(Wq, Wk, Wv, wqkvh, wqkvl);
        dim3 g1(FDIM / 256, DMODEL / 2, 2);
        pack_w_kernel<<<g1, 256>>>(W1, w1h, w1l, FDIM, DMODEL / 2);
        dim3 g2(DMODEL / 256, FDIM / 2, 2);
        pack_w_kernel<<<g2, 256>>>(W2, w2h, w2l, DMODEL, FDIM / 2);
        dim3 gc(QKVW / 256, 2);
        concat3_kernel<<<gc, 256>>>(bq, bk, bv, bqkv);
    }

    dim3 gQKV(QKVW / 128,   (M + 127) / 128);   // (24, 20)
    dim3 gF  (FDIM / 128,   (M + 127) / 128);   // (32, 20)
    dim3 gD  (DMODEL / 128, (M + 127) / 128);   // (8, 20)
    dim3 attnGrid(8, NHEAD, BATCH);

    const float* x = input;
    for (int l = 0; l < 2; l++) {
        size_t oD = (size_t)l * DMODEL;
        size_t oF = (size_t)l * FDIM;

        // LN_in: fp32 h (attn residual) + fp16 activation
        ln_kernel<<<M, 256>>>(x, ln_in_scale + oD, ln_in_bias + oD, h, ax);

        // fused QKV GEMM (fp32 out)
        gemm_fp16x2_kernel<<<gQKV, 256, GEMM_SMEM>>>(ax,
            wqkvh + l * WQKV_SZ, wqkvl + l * WQKV_SZ,
            bqkv + l * QKVW, nullptr, qkv, nullptr, M, QKVW, DMODEL);

        // attention (+h residual)
        attn_kernel<<<attnGrid, 512, 147456>>>(qkv, h, attn);

        // LN1: fp16 only
        ln_kernel<<<M, 256>>>(attn, ln1_scale + oD, ln1_bias + oD,
                              nullptr, ax);

        // W1 GEMM -> fp16 y1 (separate buffer; no aliasing)
        gemm_fp16x2_kernel<<<gF, 256, GEMM_SMEM>>>(ax,
            w1h + l * W1_SZ, w1l + l * W1_SZ,
            b1 + oF, nullptr, nullptr, y1, M, FDIM, DMODEL);

        // W2 GEMM (+attn residual, fp32 out)
        gemm_fp16x2_kernel<<<gD, 256, GEMM_SMEM>>>(y1,
            w2h + l * W2_SZ, w2l + l * W2_SZ,
            b2 + oD, attn, y2, nullptr, M, DMODEL, FDIM);

        // LN2 (fp32 only)
        float* dst = (l == 0) ? xb : (float*)d_out;
        ln_kernel<<<M, 256>>>(y2, ln2_scale + oD, ln2_bias + oD,
                              dst, nullptr);
        x = xb;
    }
}

// round 9
// speedup vs baseline: 2.0162x; 1.2704x over previous
#include <cuda_runtime.h>
#include <cuda_bf16.h>
#include <cuda_fp16.h>
#include <math.h>
#include <stdint.h>

// ---------------------------------------------------------------------------
// EmformerEncoder  B=2, T=1248, D=1024, H=16, DK=64, F=4096, L=2.
// Analytic block-sparse mask (CHUNK=128, LEFT=128, RIGHT=32).
// Round 9: MMA-count is the wall. Single-fp16 weights (x64 scale) + fp16
//          activations -> 1 MMA per k-step (half of round 8). Predicted
//          rel_err ~3.7e-4 (activation + weight rounding in quadrature).
// ---------------------------------------------------------------------------

#define TTOT   1248
#define NRIGHT 224
#define BATCH  2
#define MROWS  (BATCH * TTOT)   // 2496
#define DMODEL 1024
#define NHEAD  16
#define DK     64
#define FDIM   4096
#define QKVW   3072

// ---- scratch (device globals) ---------------------------------------------
__device__ float g_h[MROWS * DMODEL];     // LN_in fp32 (attn residual)
__device__ float g_attn[MROWS * DMODEL];
__device__ float g_y2[MROWS * DMODEL];
__device__ float g_x[MROWS * DMODEL];
__device__ float g_qkv[MROWS * QKVW];
__device__ __half g_ax[MROWS * DMODEL];   // LN fp16 activation
__device__ __half g_y1[MROWS * FDIM];     // W1 GEMM fp16 out
__device__ unsigned g_wqkv[2][(DMODEL/2) * QKVW];
__device__ unsigned g_w1[2][(DMODEL/2) * FDIM];
__device__ unsigned g_w2[2][(FDIM/2) * DMODEL];
__device__ float g_bqkv[2][QKVW];

#define WSCALE     64.0f
#define INV_WSCALE 0.015625f

// ---- helpers ---------------------------------------------------------------
__device__ __forceinline__ unsigned packh(__half a, __half b)
{
    __half2 p; p.x = a; p.y = b;
    return *(unsigned*)&p;
}
__device__ __forceinline__ void mma_f16(float* c, const unsigned* a,
                                        unsigned b0, unsigned b1)
{
    asm volatile(
        "mma.sync.aligned.m16n8k16.row.col.f32.f16.f16.f32 "
        "{%0,%1,%2,%3}, {%4,%5,%6,%7}, {%8,%9}, {%0,%1,%2,%3};"
        : "+f"(c[0]), "+f"(c[1]), "+f"(c[2]), "+f"(c[3])
        : "r"(a[0]), "r"(a[1]), "r"(a[2]), "r"(a[3]), "r"(b0), "r"(b1));
}
__device__ __forceinline__ void cp16s(uint32_t dst, const void* src, bool pred)
{
    int sz = pred ? 16 : 0;
    asm volatile("cp.async.cg.shared.global [%0], [%1], 16, %2;\n"
                 :: "r"(dst), "l"(src), "r"(sz));
}
#define CP_COMMIT() asm volatile("cp.async.commit_group;\n")

// ---------------------------------------------------------------------------
// Weight packing (x64 scale, single fp16, k-pair packed [K/2][N]).
// ---------------------------------------------------------------------------
__global__ void pack_qkv_kernel(const float* __restrict__ Wq,
                                const float* __restrict__ Wk,
                                const float* __restrict__ Wv,
                                unsigned* __restrict__ Dh)
{
    int n  = blockIdx.x * 256 + threadIdx.x;     // 0..3071
    int kp = blockIdx.y;                          // 0..511
    int l  = blockIdx.z;
    const float* W = (n < DMODEL) ? Wq : (n < 2 * DMODEL) ? Wk : Wv;
    int nc = n & (DMODEL - 1);
    W += (size_t)l * DMODEL * DMODEL;
    float e = W[(size_t)(2 * kp) * DMODEL + nc] * WSCALE;
    float o = W[(size_t)(2 * kp + 1) * DMODEL + nc] * WSCALE;
    size_t idx = (size_t)l * (DMODEL/2) * QKVW + (size_t)kp * QKVW + n;
    Dh[idx] = packh(__float2half_rn(e), __float2half_rn(o));
}

__global__ void pack_w_kernel(const float* __restrict__ W,
                              unsigned* __restrict__ Dh,
                              int N, int Khalf)
{
    int n  = blockIdx.x * 256 + threadIdx.x;
    int kp = blockIdx.y;
    int l  = blockIdx.z;
    W += (size_t)l * (2 * (size_t)Khalf) * N;
    float e = W[(size_t)(2 * kp) * N + n] * WSCALE;
    float o = W[(size_t)(2 * kp + 1) * N + n] * WSCALE;
    size_t idx = (size_t)l * Khalf * N + (size_t)kp * N + n;
    Dh[idx] = packh(__float2half_rn(e), __float2half_rn(o));
}

__global__ void concat3_kernel(const float* __restrict__ a,
                               const float* __restrict__ b,
                               const float* __restrict__ c,
                               float* __restrict__ d)
{
    int i = blockIdx.x * 256 + threadIdx.x;
    int l = blockIdx.y;
    const float* s = (i < DMODEL) ? a : (i < 2 * DMODEL) ? b : c;
    d[(size_t)l * QKVW + i] = s[(size_t)l * DMODEL + (i & (DMODEL - 1))];
}

// ---------------------------------------------------------------------------
// LayerNorm + optional fp32 out + optional fp16 out.
// ---------------------------------------------------------------------------
__global__ void ln_kernel(const float* __restrict__ X,
                          const float* __restrict__ sc,
                          const float* __restrict__ bi,
                          float* __restrict__ Yf,
                          __half* __restrict__ Yh)
{
    int row = blockIdx.x;
    int t   = threadIdx.x;
    const float4* xr = (const float4*)(X + (size_t)row * DMODEL);
    float4 v = xr[t];
    float s  = v.x + v.y + v.z + v.w;
    float ss = v.x*v.x + v.y*v.y + v.z*v.z + v.w*v.w;
    #pragma unroll
    for (int off = 16; off; off >>= 1) {
        s  += __shfl_xor_sync(0xffffffffu, s,  off);
        ss += __shfl_xor_sync(0xffffffffu, ss, off);
    }
    __shared__ float redS[8], redQ[8];
    int w = t >> 5;
    if ((t & 31) == 0) { redS[w] = s; redQ[w] = ss; }
    __syncthreads();
    float S = 0.f, Q = 0.f;
    #pragma unroll
    for (int i = 0; i < 8; i++) { S += redS[i]; Q += redQ[i]; }
    float mean = S * (1.0f / DMODEL);
    float var  = Q * (1.0f / DMODEL) - mean * mean;
    float r    = rsqrtf(var + 1e-5f);
    float4 scv = ((const float4*)sc)[t];
    float4 bv  = ((const float4*)bi)[t];
    float4 o;
    o.x = (v.x - mean) * r * scv.x + bv.x;
    o.y = (v.y - mean) * r * scv.y + bv.y;
    o.z = (v.z - mean) * r * scv.z + bv.z;
    o.w = (v.w - mean) * r * scv.w + bv.w;
    size_t base = (size_t)row * DMODEL;
    if (Yf) ((float4*)(Yf + base))[t] = o;
    if (Yh) {
        uint2 wh;
        wh.x = packh(__float2half_rn(o.x), __float2half_rn(o.y));
        wh.y = packh(__float2half_rn(o.z), __float2half_rn(o.w));
        ((uint2*)(Yh + base))[t] = wh;
    }
}

// ---------------------------------------------------------------------------
// fp16 HMMA GEMM (single-term weights).
// A: fp16 row-major [M][K]. B: packed k-pair uint32 [K/2][N] (x64 scale).
// CTA tile 128x128, BK=32, 3-stage cp.async, one barrier/iter, 2 CTAs/SM.
// Stage (words): A 128*20 = 2560 | B 16*136 = 2176  -> 4736 w = 18944 B.
// Epilogue: C = acc/64 + bias (+res)  OR fp16 out (y1).
// ---------------------------------------------------------------------------
#define ST_WORDS   4736
#define ST_BYTES   18944
#define OFF_B      2560          // words
#define GEMM_SMEM  (3 * ST_BYTES)

__global__ __launch_bounds__(256, 2)
void gemm_fp16_kernel(const __half* __restrict__ Ag,
                      const unsigned* __restrict__ Bg,
                      const float* __restrict__ bias,
                      const float* __restrict__ res,
                      float* __restrict__ C,
                      __half* __restrict__ Ch,
                      int M, int N, int K)
{
    extern __shared__ __align__(16) unsigned smw[];
    const uint32_t sb = (uint32_t)__cvta_generic_to_shared(smw);

    const int bm = blockIdx.y * 128;
    const int bn = blockIdx.x * 128;
    const int tid  = threadIdx.x;
    const int lane = tid & 31;
    const int wid  = tid >> 5;
    const int wm = (wid >> 2) * 64;
    const int wn = (wid & 3) * 32;
    const int g  = lane >> 2;
    const int qd = lane & 3;

    float acc[4][4][4];
    #pragma unroll
    for (int i = 0; i < 4; i++)
        #pragma unroll
        for (int j = 0; j < 4; j++)
            #pragma unroll
            for (int r = 0; r < 4; r++) acc[i][j][r] = 0.f;

    const int nIter = K >> 5;    // BK = 32

    // 1024 cp16 per stage -> 4 per thread
    #define LOAD_CHUNK(st, cc)                                                  \
    {                                                                           \
        uint32_t stb = sb + (st) * ST_BYTES;                                    \
        int kb = (cc) << 5;                                                     \
        _Pragma("unroll")                                                       \
        for (int j = 0; j < 4; j++) {                                           \
            int idx  = tid + j * 256;                                           \
            int part = idx >> 9;                                                \
            int sub  = idx & 511;                                               \
            if (part == 0) {                                                    \
                int row = sub >> 2, seg = sub & 3;                              \
                bool pr = (bm + row) < M;                                       \
                const __half* gp = Ag + (size_t)(bm + row) * K + kb + seg * 8;  \
                cp16s(stb + row * 80 + seg * 16, gp, pr);                       \
            } else {                                                            \
                int kp = sub >> 5, seg = sub & 31;                              \
                const unsigned* gp = Bg                                         \
                    + (size_t)((kb >> 1) + kp) * N + bn + seg * 4;              \
                cp16s(stb + 10240 + kp * 544 + seg * 16, gp, true);             \
            }                                                                   \
        }                                                                       \
    }

    LOAD_CHUNK(0, 0); CP_COMMIT();
    LOAD_CHUNK(1, 1); CP_COMMIT();

    for (int i = 0; i < nIter; i++) {
        asm volatile("cp.async.wait_group 1;\n");
        __syncthreads();
        int nx = i + 2;
        if (nx < nIter) {
            int stn = nx - (nx / 3) * 3;
            LOAD_CHUNK(stn, nx);
        }
        CP_COMMIT();

        const int s = i - (i / 3) * 3;
        const unsigned* Aw = smw + s * ST_WORDS;
        const unsigned* Bw = Aw + OFF_B;

        #pragma unroll
        for (int k16 = 0; k16 < 2; k16++) {
            unsigned af[4][4];
            #pragma unroll
            for (int mi = 0; mi < 4; mi++) {
                int ra = (wm + mi * 16 + g) * 20 + k16 * 8 + qd;
                int rb = ra + 160;
                af[mi][0] = Aw[ra];     af[mi][1] = Aw[rb];
                af[mi][2] = Aw[ra + 4]; af[mi][3] = Aw[rb + 4];
            }
            #pragma unroll
            for (int ni = 0; ni < 4; ni++) {
                int n0 = wn + ni * 8 + g;
                unsigned b0 = Bw[(k16 * 8 + qd) * 136 + n0];
                unsigned b1 = Bw[(k16 * 8 + 4 + qd) * 136 + n0];
                #pragma unroll
                for (int mi = 0; mi < 4; mi++)
                    mma_f16(acc[mi][ni], af[mi], b0, b1);
            }
        }
    }
    #undef LOAD_CHUNK

    // epilogue: scale by 1/64, bias, +res or fp16 out
    #pragma unroll
    for (int mi = 0; mi < 4; mi++) {
        #pragma unroll
        for (int ni = 0; ni < 4; ni++) {
            #pragma unroll
            for (int half_ = 0; half_ < 2; half_++) {
                int row = bm + wm + mi * 16 + g + half_ * 8;
                if (row >= M) continue;
                int cc = bn + wn + ni * 8 + qd * 2;
                float2 bb = *(const float2*)&bias[cc];
                float ox = acc[mi][ni][2 * half_ + 0] * INV_WSCALE + bb.x;
                float oy = acc[mi][ni][2 * half_ + 1] * INV_WSCALE + bb.y;
                if (Ch) {
                    size_t wi = ((size_t)row * N + cc) >> 1;
                    ((unsigned*)Ch)[wi] =
                        packh(__float2half_rn(ox), __float2half_rn(oy));
                } else {
                    if (res) {
                        float2 rr = *(const float2*)&res[(size_t)row * N + cc];
                        ox += rr.x; oy += rr.y;
                    }
                    float2 o; o.x = ox; o.y = oy;
                    *(float2*)&C[(size_t)row * N + cc] = o;
                }
            }
        }
    }
}

// ---------------------------------------------------------------------------
// Attention: warp-per-query, key-parallel lanes. 512 threads (16 warps).
// ---------------------------------------------------------------------------
__global__ __launch_bounds__(512, 1)
void attn_kernel(const float* __restrict__ qkv,
                 const float* __restrict__ Hh,
                 float* __restrict__ O)
{
    int ci = blockIdx.x;
    int hh = blockIdx.y;
    int b  = blockIdx.z;

    extern __shared__ float sm[];
    float2* Kt2 = (float2*)sm;          // [32 d-pairs][288 keys]
    float*  Vs  = sm + 18432;           // [288 keys][64]

    int nkr   = (ci < 7) ? 32 : 0;
    int body0 = (ci >= 1) ? 128 * (ci - 1) : 0;
    int nk    = nkr + (128 * (ci + 1) - body0);
    int nq    = (ci < 7) ? 160 : 128;
    int base  = b * TTOT;
    int tid   = threadIdx.x;

    if (tid < nk) {
        int key  = tid;
        int krow = (key < nkr) ? (32 * ci + key) : (NRIGHT + body0 + (key - nkr));
        const float4* kp4 = (const float4*)&qkv[(size_t)(base + krow) * QKVW + DMODEL + hh * DK];
        #pragma unroll
        for (int d4 = 0; d4 < 16; d4++) {
            float4 v = kp4[d4];
            Kt2[(2 * d4) * 288 + key]     = make_float2(v.x, v.y);
            Kt2[(2 * d4 + 1) * 288 + key] = make_float2(v.z, v.w);
        }
    }
    for (int idx = tid; idx < nk * 16; idx += 512) {
        int key = idx >> 4;
        int d4  = idx & 15;
        int krow = (key < nkr) ? (32 * ci + key) : (NRIGHT + body0 + (key - nkr));
        float4 v = *(const float4*)&qkv[(size_t)(base + krow) * QKVW + 2 * DMODEL + hh * DK + d4 * 4];
        *(float4*)&Vs[key * 64 + d4 * 4] = v;
    }
    __syncthreads();

    int warp = tid >> 5;
    int lane = tid & 31;

    for (int qi = warp; qi < nq; qi += 16) {
        int qrow;
        if (ci < 7) qrow = (qi < 32) ? (32 * ci + qi) : (NRIGHT + 128 * ci + qi - 32);
        else        qrow = NRIGHT + 128 * 7 + qi;

        const float4* qp = (const float4*)&qkv[(size_t)(base + qrow) * QKVW + hh * DK];
        float q[64];
        #pragma unroll
        for (int d4 = 0; d4 < 16; d4++) {
            float4 t = qp[d4];
            q[4*d4+0] = t.x * 0.125f;
            q[4*d4+1] = t.y * 0.125f;
            q[4*d4+2] = t.z * 0.125f;
            q[4*d4+3] = t.w * 0.125f;
        }

        float m = -1e30f, l = 0.f, o0 = 0.f, o1 = 0.f;

        for (int j0 = 0; j0 < nk; j0 += 32) {
            int key = j0 + lane;
            float s = 0.f;
            #pragma unroll
            for (int d2 = 0; d2 < 32; d2++) {
                float2 kk = Kt2[d2 * 288 + key];
                s += q[2*d2] * kk.x + q[2*d2+1] * kk.y;
            }
            float mb = s;
            #pragma unroll
            for (int off = 16; off; off >>= 1)
                mb = fmaxf(mb, __shfl_xor_sync(0xffffffffu, mb, off));
            float mnew = fmaxf(m, mb);
            float c = __expf(m - mnew);
            float p = __expf(s - mnew);
            float ps = p;
            #pragma unroll
            for (int off = 16; off; off >>= 1)
                ps += __shfl_xor_sync(0xffffffffu, ps, off);
            l = l * c + ps;
            o0 *= c; o1 *= c;
            m = mnew;
            const float2* vb = (const float2*)&Vs[j0 * 64];
            #pragma unroll
            for (int jj = 0; jj < 32; jj++) {
                float pj = __shfl_sync(0xffffffffu, p, jj);
                float2 vv = vb[jj * 32 + lane];
                o0 += pj * vv.x;
                o1 += pj * vv.y;
            }
        }

        float inv = 1.0f / l;
        size_t ooff = (size_t)(base + qrow) * QKVW;  // unused; recompute below
        ooff = (size_t)(base + qrow) * DMODEL + hh * DK + 2 * lane;
        float2 hv = *(const float2*)&Hh[ooff];
        float2 out;
        out.x = o0 * inv + hv.x;
        out.y = o1 * inv + hv.y;
        *(float2*)&O[ooff] = out;
    }
}

// ---------------------------------------------------------------------------
extern "C" void kernel_launch(void* const* d_in, const int* in_sizes, int n_in,
                              void* d_out, int out_size)
{
    const float* input       = (const float*)d_in[0];
    const float* ln_in_scale = (const float*)d_in[1];
    const float* ln_in_bias  = (const float*)d_in[2];
    const float* Wq          = (const float*)d_in[3];
    const float* bq          = (const float*)d_in[4];
    const float* Wk          = (const float*)d_in[5];
    const float* bk          = (const float*)d_in[6];
    const float* Wv          = (const float*)d_in[7];
    const float* bv          = (const float*)d_in[8];
    const float* ln1_scale   = (const float*)d_in[9];
    const float* ln1_bias    = (const float*)d_in[10];
    const float* W1          = (const float*)d_in[11];
    const float* b1          = (const float*)d_in[12];
    const float* W2          = (const float*)d_in[13];
    const float* b2          = (const float*)d_in[14];
    const float* ln2_scale   = (const float*)d_in[15];
    const float* ln2_bias    = (const float*)d_in[16];
    // d_in[17] = mask: unused (analytic)

    float *h, *attn, *y2, *xb, *qkv, *bqkv;
    __half *ax, *y1;
    unsigned *wqkv, *w1, *w2;
    cudaGetSymbolAddress((void**)&h,    g_h);
    cudaGetSymbolAddress((void**)&attn, g_attn);
    cudaGetSymbolAddress((void**)&y2,   g_y2);
    cudaGetSymbolAddress((void**)&xb,   g_x);
    cudaGetSymbolAddress((void**)&qkv,  g_qkv);
    cudaGetSymbolAddress((void**)&ax,   g_ax);
    cudaGetSymbolAddress((void**)&y1,   g_y1);
    cudaGetSymbolAddress((void**)&wqkv, g_wqkv);
    cudaGetSymbolAddress((void**)&w1,   g_w1);
    cudaGetSymbolAddress((void**)&w2,   g_w2);
    cudaGetSymbolAddress((void**)&bqkv, g_bqkv);

    cudaFuncSetAttribute(attn_kernel,
                         cudaFuncAttributeMaxDynamicSharedMemorySize, 147456);
    cudaFuncSetAttribute(gemm_fp16_kernel,
                         cudaFuncAttributeMaxDynamicSharedMemorySize, GEMM_SMEM);

    const int M = MROWS;
    const size_t WQKV_SZ = (size_t)(DMODEL/2) * QKVW;
    const size_t W1_SZ   = (size_t)(DMODEL/2) * FDIM;
    const size_t W2_SZ   = (size_t)(FDIM/2) * DMODEL;

    // ---- weight packing: 3 launches + bias concat (both layers each) -------
    {
        dim3 gq(QKVW / 256, DMODEL / 2, 2);
        pack_qkv_kernel<<<gq, 256>>>(Wq, Wk, Wv, wqkv);
        dim3 g1(FDIM / 256, DMODEL / 2, 2);
        pack_w_kernel<<<g1, 256>>>(W1, w1, FDIM, DMODEL / 2);
        dim3 g2(DMODEL / 256, FDIM / 2, 2);
        pack_w_kernel<<<g2, 256>>>(W2, w2, DMODEL, FDIM / 2);
        dim3 gc(QKVW / 256, 2);
        concat3_kernel<<<gc, 256>>>(bq, bk, bv, bqkv);
    }

    dim3 gQKV(QKVW / 128,   (M + 127) / 128);   // (24, 20)
    dim3 gF  (FDIM / 128,   (M + 127) / 128);   // (32, 20)
    dim3 gD  (DMODEL / 128, (M + 127) / 128);   // (8, 20)
    dim3 attnGrid(8, NHEAD, BATCH);

    const float* x = input;
    for (int l = 0; l < 2; l++) {
        size_t oD = (size_t)l * DMODEL;
        size_t oF = (size_t)l * FDIM;

        // LN_in: fp32 h (attn residual) + fp16 activation
        ln_kernel<<<M, 256>>>(x, ln_in_scale + oD, ln_in_bias + oD, h, ax);

        // fused QKV GEMM (fp32 out)
        gemm_fp16_kernel<<<gQKV, 256, GEMM_SMEM>>>(ax,
            wqkv + l * WQKV_SZ,
            bqkv + l * QKVW, nullptr, qkv, nullptr, M, QKVW, DMODEL);

        // attention (+h residual)
        attn_kernel<<<attnGrid, 512, 147456>>>(qkv, h, attn);

        // LN1: fp16 only
        ln_kernel<<<M, 256>>>(attn, ln1_scale + oD, ln1_bias + oD,
                              nullptr, ax);

        // W1 GEMM -> fp16 y1 (separate buffer; no aliasing)
        gemm_fp16_kernel<<<gF, 256, GEMM_SMEM>>>(ax,
            w1 + l * W1_SZ,
            b1 + oF, nullptr, nullptr, y1, M, FDIM, DMODEL);

        // W2 GEMM (+attn residual, fp32 out)
        gemm_fp16_kernel<<<gD, 256, GEMM_SMEM>>>(y1,
            w2 + l * W2_SZ,
            b2 + oD, attn, y2, nullptr, M, DMODEL, FDIM);

        // LN2 (fp32 only)
        float* dst = (l == 0) ? xb : (float*)d_out;
        ln_kernel<<<M, 256>>>(y2, ln2_scale + oD, ln2_bias + oD,
                              dst, nullptr);
        x = xb;
    }
}

// round 11
// speedup vs baseline: 3.4155x; 1.6941x over previous
#include <cuda_runtime.h>
#include <cuda_fp16.h>
#include <math.h>
#include <stdint.h>

// ---------------------------------------------------------------------------
// EmformerEncoder  B=2, T=1248, D=1024, H=16, DK=64, F=4096, L=2.
// Analytic block-sparse mask (CHUNK=128, LEFT=128, RIGHT=32).
// Round 10: attention moved to HMMA (fp16 QK^T / PV, fp32 online softmax).
//           GEMM path unchanged from round 9 (single-fp16 weights, x64).
// ---------------------------------------------------------------------------

#define TTOT   1248
#define NRIGHT 224
#define BATCH  2
#define MROWS  (BATCH * TTOT)   // 2496
#define DMODEL 1024
#define NHEAD  16
#define DK     64
#define FDIM   4096
#define QKVW   3072

// ---- scratch (device globals) ---------------------------------------------
__device__ float g_h[MROWS * DMODEL];     // LN_in fp32 (attn residual)
__device__ float g_attn[MROWS * DMODEL];
__device__ float g_y2[MROWS * DMODEL];
__device__ float g_x[MROWS * DMODEL];
__device__ float g_qkv[MROWS * QKVW];
__device__ __half g_ax[MROWS * DMODEL];   // LN fp16 activation
__device__ __half g_y1[MROWS * FDIM];     // W1 GEMM fp16 out
__device__ unsigned g_wqkv[2][(DMODEL/2) * QKVW];
__device__ unsigned g_w1[2][(DMODEL/2) * FDIM];
__device__ unsigned g_w2[2][(FDIM/2) * DMODEL];
__device__ float g_bqkv[2][QKVW];

#define WSCALE     64.0f
#define INV_WSCALE 0.015625f

// ---- helpers ---------------------------------------------------------------
__device__ __forceinline__ unsigned packh(__half a, __half b)
{
    __half2 p; p.x = a; p.y = b;
    return *(unsigned*)&p;
}
__device__ __forceinline__ unsigned packf2h(float a, float b)
{
    __half2 p = __floats2half2_rn(a, b);
    return *(unsigned*)&p;
}
__device__ __forceinline__ void mma_f16(float* c, const unsigned* a,
                                        unsigned b0, unsigned b1)
{
    asm volatile(
        "mma.sync.aligned.m16n8k16.row.col.f32.f16.f16.f32 "
        "{%0,%1,%2,%3}, {%4,%5,%6,%7}, {%8,%9}, {%0,%1,%2,%3};"
        : "+f"(c[0]), "+f"(c[1]), "+f"(c[2]), "+f"(c[3])
        : "r"(a[0]), "r"(a[1]), "r"(a[2]), "r"(a[3]), "r"(b0), "r"(b1));
}
__device__ __forceinline__ void cp16s(uint32_t dst, const void* src, bool pred)
{
    int sz = pred ? 16 : 0;
    asm volatile("cp.async.cg.shared.global [%0], [%1], 16, %2;\n"
                 :: "r"(dst), "l"(src), "r"(sz));
}
#define CP_COMMIT() asm volatile("cp.async.commit_group;\n")

// ---------------------------------------------------------------------------
// Weight packing (x64 scale, single fp16, k-pair packed [K/2][N]).
// ---------------------------------------------------------------------------
__global__ void pack_qkv_kernel(const float* __restrict__ Wq,
                                const float* __restrict__ Wk,
                                const float* __restrict__ Wv,
                                unsigned* __restrict__ Dh)
{
    int n  = blockIdx.x * 256 + threadIdx.x;     // 0..3071
    int kp = blockIdx.y;                          // 0..511
    int l  = blockIdx.z;
    const float* W = (n < DMODEL) ? Wq : (n < 2 * DMODEL) ? Wk : Wv;
    int nc = n & (DMODEL - 1);
    W += (size_t)l * DMODEL * DMODEL;
    float e = W[(size_t)(2 * kp) * DMODEL + nc] * WSCALE;
    float o = W[(size_t)(2 * kp + 1) * DMODEL + nc] * WSCALE;
    size_t idx = (size_t)l * (DMODEL/2) * QKVW + (size_t)kp * QKVW + n;
    Dh[idx] = packf2h(e, o);
}

__global__ void pack_w_kernel(const float* __restrict__ W,
                              unsigned* __restrict__ Dh,
                              int N, int Khalf)
{
    int n  = blockIdx.x * 256 + threadIdx.x;
    int kp = blockIdx.y;
    int l  = blockIdx.z;
    W += (size_t)l * (2 * (size_t)Khalf) * N;
    float e = W[(size_t)(2 * kp) * N + n] * WSCALE;
    float o = W[(size_t)(2 * kp + 1) * N + n] * WSCALE;
    size_t idx = (size_t)l * Khalf * N + (size_t)kp * N + n;
    Dh[idx] = packf2h(e, o);
}

__global__ void concat3_kernel(const float* __restrict__ a,
                               const float* __restrict__ b,
                               const float* __restrict__ c,
                               float* __restrict__ d)
{
    int i = blockIdx.x * 256 + threadIdx.x;
    int l = blockIdx.y;
    const float* s = (i < DMODEL) ? a : (i < 2 * DMODEL) ? b : c;
    d[(size_t)l * QKVW + i] = s[(size_t)l * DMODEL + (i & (DMODEL - 1))];
}

// ---------------------------------------------------------------------------
// LayerNorm + optional fp32 out + optional fp16 out.
// ---------------------------------------------------------------------------
__global__ void ln_kernel(const float* __restrict__ X,
                          const float* __restrict__ sc,
                          const float* __restrict__ bi,
                          float* __restrict__ Yf,
                          __half* __restrict__ Yh)
{
    int row = blockIdx.x;
    int t   = threadIdx.x;
    const float4* xr = (const float4*)(X + (size_t)row * DMODEL);
    float4 v = xr[t];
    float s  = v.x + v.y + v.z + v.w;
    float ss = v.x*v.x + v.y*v.y + v.z*v.z + v.w*v.w;
    #pragma unroll
    for (int off = 16; off; off >>= 1) {
        s  += __shfl_xor_sync(0xffffffffu, s,  off);
        ss += __shfl_xor_sync(0xffffffffu, ss, off);
    }
    __shared__ float redS[8], redQ[8];
    int w = t >> 5;
    if ((t & 31) == 0) { redS[w] = s; redQ[w] = ss; }
    __syncthreads();
    float S = 0.f, Q = 0.f;
    #pragma unroll
    for (int i = 0; i < 8; i++) { S += redS[i]; Q += redQ[i]; }
    float mean = S * (1.0f / DMODEL);
    float var  = Q * (1.0f / DMODEL) - mean * mean;
    float r    = rsqrtf(var + 1e-5f);
    float4 scv = ((const float4*)sc)[t];
    float4 bv  = ((const float4*)bi)[t];
    float4 o;
    o.x = (v.x - mean) * r * scv.x + bv.x;
    o.y = (v.y - mean) * r * scv.y + bv.y;
    o.z = (v.z - mean) * r * scv.z + bv.z;
    o.w = (v.w - mean) * r * scv.w + bv.w;
    size_t base = (size_t)row * DMODEL;
    if (Yf) ((float4*)(Yf + base))[t] = o;
    if (Yh) {
        uint2 wh;
        wh.x = packf2h(o.x, o.y);
        wh.y = packf2h(o.z, o.w);
        ((uint2*)(Yh + base))[t] = wh;
    }
}

// ---------------------------------------------------------------------------
// fp16 HMMA GEMM (single-term weights).  (unchanged from round 9)
// ---------------------------------------------------------------------------
#define ST_WORDS   4736
#define ST_BYTES   18944
#define OFF_B      2560          // words
#define GEMM_SMEM  (3 * ST_BYTES)

__global__ __launch_bounds__(256, 2)
void gemm_fp16_kernel(const __half* __restrict__ Ag,
                      const unsigned* __restrict__ Bg,
                      const float* __restrict__ bias,
                      const float* __restrict__ res,
                      float* __restrict__ C,
                      __half* __restrict__ Ch,
                      int M, int N, int K)
{
    extern __shared__ __align__(16) unsigned smw[];
    const uint32_t sb = (uint32_t)__cvta_generic_to_shared(smw);

    const int bm = blockIdx.y * 128;
    const int bn = blockIdx.x * 128;
    const int tid  = threadIdx.x;
    const int lane = tid & 31;
    const int wid  = tid >> 5;
    const int wm = (wid >> 2) * 64;
    const int wn = (wid & 3) * 32;
    const int g  = lane >> 2;
    const int qd = lane & 3;

    float acc[4][4][4];
    #pragma unroll
    for (int i = 0; i < 4; i++)
        #pragma unroll
        for (int j = 0; j < 4; j++)
            #pragma unroll
            for (int r = 0; r < 4; r++) acc[i][j][r] = 0.f;

    const int nIter = K >> 5;    // BK = 32

    #define LOAD_CHUNK(st, cc)                                                  \
    {                                                                           \
        uint32_t stb = sb + (st) * ST_BYTES;                                    \
        int kb = (cc) << 5;                                                     \
        _Pragma("unroll")                                                       \
        for (int j = 0; j < 4; j++) {                                           \
            int idx  = tid + j * 256;                                           \
            int part = idx >> 9;                                                \
            int sub  = idx & 511;                                               \
            if (part == 0) {                                                    \
                int row = sub >> 2, seg = sub & 3;                              \
                bool pr = (bm + row) < M;                                       \
                const __half* gp = Ag + (size_t)(bm + row) * K + kb + seg * 8;  \
                cp16s(stb + row * 80 + seg * 16, gp, pr);                       \
            } else {                                                            \
                int kp = sub >> 5, seg = sub & 31;                              \
                const unsigned* gp = Bg                                         \
                    + (size_t)((kb >> 1) + kp) * N + bn + seg * 4;              \
                cp16s(stb + 10240 + kp * 544 + seg * 16, gp, true);             \
            }                                                                   \
        }                                                                       \
    }

    LOAD_CHUNK(0, 0); CP_COMMIT();
    LOAD_CHUNK(1, 1); CP_COMMIT();

    for (int i = 0; i < nIter; i++) {
        asm volatile("cp.async.wait_group 1;\n");
        __syncthreads();
        int nx = i + 2;
        if (nx < nIter) {
            int stn = nx - (nx / 3) * 3;
            LOAD_CHUNK(stn, nx);
        }
        CP_COMMIT();

        const int s = i - (i / 3) * 3;
        const unsigned* Aw = smw + s * ST_WORDS;
        const unsigned* Bw = Aw + OFF_B;

        #pragma unroll
        for (int k16 = 0; k16 < 2; k16++) {
            unsigned af[4][4];
            #pragma unroll
            for (int mi = 0; mi < 4; mi++) {
                int ra = (wm + mi * 16 + g) * 20 + k16 * 8 + qd;
                int rb = ra + 160;
                af[mi][0] = Aw[ra];     af[mi][1] = Aw[rb];
                af[mi][2] = Aw[ra + 4]; af[mi][3] = Aw[rb + 4];
            }
            #pragma unroll
            for (int ni = 0; ni < 4; ni++) {
                int n0 = wn + ni * 8 + g;
                unsigned b0 = Bw[(k16 * 8 + qd) * 136 + n0];
                unsigned b1 = Bw[(k16 * 8 + 4 + qd) * 136 + n0];
                #pragma unroll
                for (int mi = 0; mi < 4; mi++)
                    mma_f16(acc[mi][ni], af[mi], b0, b1);
            }
        }
    }
    #undef LOAD_CHUNK

    #pragma unroll
    for (int mi = 0; mi < 4; mi++) {
        #pragma unroll
        for (int ni = 0; ni < 4; ni++) {
            #pragma unroll
            for (int half_ = 0; half_ < 2; half_++) {
                int row = bm + wm + mi * 16 + g + half_ * 8;
                if (row >= M) continue;
                int cc = bn + wn + ni * 8 + qd * 2;
                float2 bb = *(const float2*)&bias[cc];
                float ox = acc[mi][ni][2 * half_ + 0] * INV_WSCALE + bb.x;
                float oy = acc[mi][ni][2 * half_ + 1] * INV_WSCALE + bb.y;
                if (Ch) {
                    size_t wi = ((size_t)row * N + cc) >> 1;
                    ((unsigned*)Ch)[wi] = packf2h(ox, oy);
                } else {
                    if (res) {
                        float2 rr = *(const float2*)&res[(size_t)row * N + cc];
                        ox += rr.x; oy += rr.y;
                    }
                    float2 o; o.x = ox; o.y = oy;
                    *(float2*)&C[(size_t)row * N + cc] = o;
                }
            }
        }
    }
}

// ---------------------------------------------------------------------------
// HMMA attention.  Block = (chunk, head, batch), 256 threads (8 warps),
// 2 CTAs/SM.  Warp = 16-query tile (tiles w, w+8).  Keys in 32-blocks with
// online softmax; QK^T and PV on m16n8k16 HMMA (fp16 in, fp32 accum).
// smem: Kt [nk][72] halves (row-major K), Vt [64][296] halves (transposed V).
// nq in {160,128}, nk in {160,288,256} — all exact tile multiples, no masks.
// ---------------------------------------------------------------------------
#define KT_STRIDE 72
#define VT_STRIDE 296
#define ATT_SMEM  (288 * KT_STRIDE * 2 + 64 * VT_STRIDE * 2)   // 79360 B

__device__ __forceinline__ int qmap(int ci, int qi)
{
    if (ci < 7) return (qi < 32) ? (32 * ci + qi) : (NRIGHT + 128 * ci + qi - 32);
    return NRIGHT + 128 * 7 + qi;
}

__global__ __launch_bounds__(256, 2)
void attn_kernel(const float* __restrict__ qkv,
                 const float* __restrict__ Hh,
                 float* __restrict__ O)
{
    int ci = blockIdx.x;
    int hh = blockIdx.y;
    int b  = blockIdx.z;

    extern __shared__ __half ash[];
    __half* Kt = ash;                       // [nk][KT_STRIDE]
    __half* Vt = ash + 288 * KT_STRIDE;     // [64][VT_STRIDE]

    int nkr   = (ci < 7) ? 32 : 0;
    int body0 = (ci >= 1) ? 128 * (ci - 1) : 0;
    int nk    = nkr + (128 * (ci + 1) - body0);
    int nq    = (ci < 7) ? 160 : 128;
    int base  = b * TTOT;
    int tid   = threadIdx.x;

    // ---- stage K (row-major fp16) and V (transposed fp16) ------------------
    for (int idx = tid; idx < nk * 16; idx += 256) {
        int key = idx >> 4;
        int d4  = idx & 15;
        int krow = (key < nkr) ? (32 * ci + key) : (NRIGHT + body0 + (key - nkr));
        size_t roff = (size_t)(base + krow) * QKVW + hh * DK + d4 * 4;
        float4 kv = *(const float4*)&qkv[roff + DMODEL];
        uint2 kw;
        kw.x = packf2h(kv.x, kv.y);
        kw.y = packf2h(kv.z, kv.w);
        *(uint2*)&Kt[key * KT_STRIDE + d4 * 4] = kw;
        float4 vv = *(const float4*)&qkv[roff + 2 * DMODEL];
        Vt[(4 * d4 + 0) * VT_STRIDE + key] = __float2half_rn(vv.x);
        Vt[(4 * d4 + 1) * VT_STRIDE + key] = __float2half_rn(vv.y);
        Vt[(4 * d4 + 2) * VT_STRIDE + key] = __float2half_rn(vv.z);
        Vt[(4 * d4 + 3) * VT_STRIDE + key] = __float2half_rn(vv.w);
    }
    __syncthreads();

    int warp = tid >> 5;
    int lane = tid & 31;
    int g    = lane >> 2;
    int qd   = lane & 3;
    int ntiles = nq >> 4;

    for (int t = warp; t < ntiles; t += 8) {
        int rlo = qmap(ci, t * 16 + g);
        int rhi = qmap(ci, t * 16 + g + 8);

        // Q fragments (x 1/8 scale), 4 k-steps over DK=64
        unsigned aq[4][4];
        const float* Qlo = qkv + (size_t)(base + rlo) * QKVW + hh * DK;
        const float* Qhi = qkv + (size_t)(base + rhi) * QKVW + hh * DK;
        #pragma unroll
        for (int ks = 0; ks < 4; ks++) {
            int c0 = 16 * ks + 2 * qd;
            float2 l0 = *(const float2*)(Qlo + c0);
            float2 h0 = *(const float2*)(Qhi + c0);
            float2 l1 = *(const float2*)(Qlo + c0 + 8);
            float2 h1 = *(const float2*)(Qhi + c0 + 8);
            aq[ks][0] = packf2h(l0.x * 0.125f, l0.y * 0.125f);
            aq[ks][1] = packf2h(h0.x * 0.125f, h0.y * 0.125f);
            aq[ks][2] = packf2h(l1.x * 0.125f, l1.y * 0.125f);
            aq[ks][3] = packf2h(h1.x * 0.125f, h1.y * 0.125f);
        }

        float m0 = -1e30f, m1 = -1e30f, l0 = 0.f, l1 = 0.f;
        float o[8][4];
        #pragma unroll
        for (int nt = 0; nt < 8; nt++)
            #pragma unroll
            for (int r = 0; r < 4; r++) o[nt][r] = 0.f;

        for (int kb = 0; kb < nk; kb += 32) {
            // ---- S = Q K^T  (m16 x n32) --------------------------------------
            float s[4][4];
            #pragma unroll
            for (int nt = 0; nt < 4; nt++)
                #pragma unroll
                for (int r = 0; r < 4; r++) s[nt][r] = 0.f;
            #pragma unroll
            for (int ks = 0; ks < 4; ks++) {
                #pragma unroll
                for (int nt = 0; nt < 4; nt++) {
                    const __half* kr = &Kt[(kb + nt * 8 + g) * KT_STRIDE + 16 * ks + 2 * qd];
                    unsigned b0 = *(const unsigned*)kr;
                    unsigned b1 = *(const unsigned*)(kr + 8);
                    mma_f16(s[nt], aq[ks], b0, b1);
                }
            }
            // ---- online softmax ---------------------------------------------
            float mx0 = s[0][0], mx1 = s[0][2];
            #pragma unroll
            for (int nt = 0; nt < 4; nt++) {
                mx0 = fmaxf(mx0, fmaxf(s[nt][0], s[nt][1]));
                mx1 = fmaxf(mx1, fmaxf(s[nt][2], s[nt][3]));
            }
            mx0 = fmaxf(mx0, __shfl_xor_sync(0xffffffffu, mx0, 1));
            mx0 = fmaxf(mx0, __shfl_xor_sync(0xffffffffu, mx0, 2));
            mx1 = fmaxf(mx1, __shfl_xor_sync(0xffffffffu, mx1, 1));
            mx1 = fmaxf(mx1, __shfl_xor_sync(0xffffffffu, mx1, 2));
            float mn0 = fmaxf(m0, mx0), mn1 = fmaxf(m1, mx1);
            float c0 = __expf(m0 - mn0), c1 = __expf(m1 - mn1);
            m0 = mn0; m1 = mn1;
            float ps0 = 0.f, ps1 = 0.f;
            #pragma unroll
            for (int nt = 0; nt < 4; nt++) {
                s[nt][0] = __expf(s[nt][0] - mn0);
                s[nt][1] = __expf(s[nt][1] - mn0);
                s[nt][2] = __expf(s[nt][2] - mn1);
                s[nt][3] = __expf(s[nt][3] - mn1);
                ps0 += s[nt][0] + s[nt][1];
                ps1 += s[nt][2] + s[nt][3];
            }
            ps0 += __shfl_xor_sync(0xffffffffu, ps0, 1);
            ps0 += __shfl_xor_sync(0xffffffffu, ps0, 2);
            ps1 += __shfl_xor_sync(0xffffffffu, ps1, 1);
            ps1 += __shfl_xor_sync(0xffffffffu, ps1, 2);
            l0 = l0 * c0 + ps0;
            l1 = l1 * c1 + ps1;
            #pragma unroll
            for (int nt = 0; nt < 8; nt++) {
                o[nt][0] *= c0; o[nt][1] *= c0;
                o[nt][2] *= c1; o[nt][3] *= c1;
            }
            // ---- P fragments (C-layout -> A-layout repack) -------------------
            unsigned pa[2][4];
            #pragma unroll
            for (int kt = 0; kt < 2; kt++) {
                pa[kt][0] = packf2h(s[2 * kt][0],     s[2 * kt][1]);
                pa[kt][1] = packf2h(s[2 * kt][2],     s[2 * kt][3]);
                pa[kt][2] = packf2h(s[2 * kt + 1][0], s[2 * kt + 1][1]);
                pa[kt][3] = packf2h(s[2 * kt + 1][2], s[2 * kt + 1][3]);
            }
            // ---- O += P V  (m16 x n64, k32) ----------------------------------
            #pragma unroll
            for (int kt = 0; kt < 2; kt++) {
                #pragma unroll
                for (int nt = 0; nt < 8; nt++) {
                    const __half* vr = &Vt[(nt * 8 + g) * VT_STRIDE + kb + 16 * kt + 2 * qd];
                    unsigned b0 = *(const unsigned*)vr;
                    unsigned b1 = *(const unsigned*)(vr + 8);
                    mma_f16(o[nt], pa[kt], b0, b1);
                }
            }
        }

        // ---- normalize + residual + store -----------------------------------
        float i0 = 1.0f / l0, i1 = 1.0f / l1;
        size_t olo = (size_t)(base + rlo) * DMODEL + hh * DK;
        size_t ohi = (size_t)(base + rhi) * DMODEL + hh * DK;
        #pragma unroll
        for (int nt = 0; nt < 8; nt++) {
            int cc = nt * 8 + 2 * qd;
            float2 hv = *(const float2*)&Hh[olo + cc];
            float2 out;
            out.x = o[nt][0] * i0 + hv.x;
            out.y = o[nt][1] * i0 + hv.y;
            *(float2*)&O[olo + cc] = out;
            hv = *(const float2*)&Hh[ohi + cc];
            out.x = o[nt][2] * i1 + hv.x;
            out.y = o[nt][3] * i1 + hv.y;
            *(float2*)&O[ohi + cc] = out;
        }
    }
}

// ---------------------------------------------------------------------------
extern "C" void kernel_launch(void* const* d_in, const int* in_sizes, int n_in,
                              void* d_out, int out_size)
{
    const float* input       = (const float*)d_in[0];
    const float* ln_in_scale = (const float*)d_in[1];
    const float* ln_in_bias  = (const float*)d_in[2];
    const float* Wq          = (const float*)d_in[3];
    const float* bq          = (const float*)d_in[4];
    const float* Wk          = (const float*)d_in[5];
    const float* bk          = (const float*)d_in[6];
    const float* Wv          = (const float*)d_in[7];
    const float* bv          = (const float*)d_in[8];
    const float* ln1_scale   = (const float*)d_in[9];
    const float* ln1_bias    = (const float*)d_in[10];
    const float* W1          = (const float*)d_in[11];
    const float* b1          = (const float*)d_in[12];
    const float* W2          = (const float*)d_in[13];
    const float* b2          = (const float*)d_in[14];
    const float* ln2_scale   = (const float*)d_in[15];
    const float* ln2_bias    = (const float*)d_in[16];
    // d_in[17] = mask: unused (analytic)

    float *h, *attn, *y2, *xb, *qkv, *bqkv;
    __half *ax, *y1;
    unsigned *wqkv, *w1, *w2;
    cudaGetSymbolAddress((void**)&h,    g_h);
    cudaGetSymbolAddress((void**)&attn, g_attn);
    cudaGetSymbolAddress((void**)&y2,   g_y2);
    cudaGetSymbolAddress((void**)&xb,   g_x);
    cudaGetSymbolAddress((void**)&qkv,  g_qkv);
    cudaGetSymbolAddress((void**)&ax,   g_ax);
    cudaGetSymbolAddress((void**)&y1,   g_y1);
    cudaGetSymbolAddress((void**)&wqkv, g_wqkv);
    cudaGetSymbolAddress((void**)&w1,   g_w1);
    cudaGetSymbolAddress((void**)&w2,   g_w2);
    cudaGetSymbolAddress((void**)&bqkv, g_bqkv);

    cudaFuncSetAttribute(attn_kernel,
                         cudaFuncAttributeMaxDynamicSharedMemorySize, ATT_SMEM);
    cudaFuncSetAttribute(gemm_fp16_kernel,
                         cudaFuncAttributeMaxDynamicSharedMemorySize, GEMM_SMEM);

    const int M = MROWS;
    const size_t WQKV_SZ = (size_t)(DMODEL/2) * QKVW;
    const size_t W1_SZ   = (size_t)(DMODEL/2) * FDIM;
    const size_t W2_SZ   = (size_t)(FDIM/2) * DMODEL;

    // ---- weight packing: 3 launches + bias concat (both layers each) -------
    {
        dim3 gq(QKVW / 256, DMODEL / 2, 2);
        pack_qkv_kernel<<<gq, 256>>>(Wq, Wk, Wv, wqkv);
        dim3 g1(FDIM / 256, DMODEL / 2, 2);
        pack_w_kernel<<<g1, 256>>>(W1, w1, FDIM, DMODEL / 2);
        dim3 g2(DMODEL / 256, FDIM / 2, 2);
        pack_w_kernel<<<g2, 256>>>(W2, w2, DMODEL, FDIM / 2);
        dim3 gc(QKVW / 256, 2);
        concat3_kernel<<<gc, 256>>>(bq, bk, bv, bqkv);
    }

    dim3 gQKV(QKVW / 128,   (M + 127) / 128);   // (24, 20)
    dim3 gF  (FDIM / 128,   (M + 127) / 128);   // (32, 20)
    dim3 gD  (DMODEL / 128, (M + 127) / 128);   // (8, 20)
    dim3 attnGrid(8, NHEAD, BATCH);

    const float* x = input;
    for (int l = 0; l < 2; l++) {
        size_t oD = (size_t)l * DMODEL;
        size_t oF = (size_t)l * FDIM;

        // LN_in: fp32 h (attn residual) + fp16 activation
        ln_kernel<<<M, 256>>>(x, ln_in_scale + oD, ln_in_bias + oD, h, ax);

        // fused QKV GEMM (fp32 out)
        gemm_fp16_kernel<<<gQKV, 256, GEMM_SMEM>>>(ax,
            wqkv + l * WQKV_SZ,
            bqkv + l * QKVW, nullptr, qkv, nullptr, M, QKVW, DMODEL);

        // attention (+h residual), HMMA
        attn_kernel<<<attnGrid, 256, ATT_SMEM>>>(qkv, h, attn);

        // LN1: fp16 only
        ln_kernel<<<M, 256>>>(attn, ln1_scale + oD, ln1_bias + oD,
                              nullptr, ax);

        // W1 GEMM -> fp16 y1 (separate buffer; no aliasing)
        gemm_fp16_kernel<<<gF, 256, GEMM_SMEM>>>(ax,
            w1 + l * W1_SZ,
            b1 + oF, nullptr, nullptr, y1, M, FDIM, DMODEL);

        // W2 GEMM (+attn residual, fp32 out)
        gemm_fp16_kernel<<<gD, 256, GEMM_SMEM>>>(y1,
            w2 + l * W2_SZ,
            b2 + oD, attn, y2, nullptr, M, DMODEL, FDIM);

        // LN2 (fp32 only)
        float* dst = (l == 0) ? xb : (float*)d_out;
        ln_kernel<<<M, 256>>>(y2, ln2_scale + oD, ln2_bias + oD,
                              dst, nullptr);
        x = xb;
    }
}